// round 5
// baseline (speedup 1.0000x reference)
#include <cuda_runtime.h>
#include <cuda_bf16.h>
#include <math.h>
#include <stdint.h>

#define NROWS 65536

// ---------------- scratch (device globals; no allocation allowed) ----------
__device__ float  g_psum[128 * 768];
__device__ float  g_psumsq[128 * 768];
__device__ float  g_scale[768];
__device__ float  g_shift[768];
__device__ __nv_bfloat16 g_xh[(size_t)NROWS * 768];
__device__ __nv_bfloat16 g_xl[(size_t)NROWS * 768];
__device__ __nv_bfloat16 g_W0h[1536 * 768];
__device__ __nv_bfloat16 g_W0l[1536 * 768];
__device__ __nv_bfloat16 g_W1h[1536 * 512];
__device__ __nv_bfloat16 g_W1l[1536 * 512];
__device__ __nv_bfloat16 g_h1h[(size_t)NROWS * 512];
__device__ __nv_bfloat16 g_h1l[(size_t)NROWS * 512];
__device__ float g_h2[(size_t)NROWS * 512];
__device__ float g_gc0[1536];
__device__ float g_gc1[1536];

// ---------------- helpers ----------------
__device__ __forceinline__ uint32_t smem_u32(const void* p) {
    uint32_t a;
    asm("{ .reg .u64 t; cvta.to.shared.u64 t, %1; cvt.u32.u64 %0, t; }" : "=r"(a) : "l"(p));
    return a;
}
__device__ __forceinline__ void cpasync16(uint32_t dst, const void* src) {
    asm volatile("cp.async.cg.shared.global [%0], [%1], 16;" :: "r"(dst), "l"(src));
}
#define CP_COMMIT() asm volatile("cp.async.commit_group;")

__device__ __forceinline__ void ldsm4(uint32_t& r0, uint32_t& r1, uint32_t& r2,
                                      uint32_t& r3, uint32_t addr) {
    asm volatile("ldmatrix.sync.aligned.m8n8.x4.shared.b16 {%0,%1,%2,%3}, [%4];"
                 : "=r"(r0), "=r"(r1), "=r"(r2), "=r"(r3) : "r"(addr));
}
__device__ __forceinline__ void mma16816(float* c, const uint32_t* a, const uint32_t* b) {
    asm volatile("mma.sync.aligned.m16n8k16.row.col.f32.bf16.bf16.f32 "
                 "{%0,%1,%2,%3}, {%4,%5,%6,%7}, {%8,%9}, {%0,%1,%2,%3};"
                 : "+f"(c[0]), "+f"(c[1]), "+f"(c[2]), "+f"(c[3])
                 : "r"(a[0]), "r"(a[1]), "r"(a[2]), "r"(a[3]), "r"(b[0]), "r"(b[1]));
}

// ---------------- BN stats (no pre-zero: per-block partials) ----------------
__global__ void stats_kernel(const float* __restrict__ x, int rowsPerBlock, int nrows) {
    int c = threadIdx.x;                       // 768 threads: one per feature
    int b = blockIdx.x;
    long r0 = (long)b * rowsPerBlock;
    float s = 0.f, s2 = 0.f;
    for (int r = 0; r < rowsPerBlock; ++r) {
        long row = r0 + r;
        if (row < nrows) {
            float v = x[row * 768 + c];
            s += v; s2 += v * v;
        }
    }
    g_psum[b * 768 + c] = s;
    g_psumsq[b * 768 + c] = s2;
}

__global__ void prep_kernel(const float* __restrict__ gamma,
                            const float* __restrict__ beta, int nrows, int nblk) {
    int c = threadIdx.x;
    double s = 0.0, s2 = 0.0;
    for (int b = 0; b < nblk; ++b) {
        s  += (double)g_psum[b * 768 + c];
        s2 += (double)g_psumsq[b * 768 + c];
    }
    double mean = s / (double)nrows;
    double var  = s2 / (double)nrows - mean * mean;
    float sc = gamma[c] * (float)(1.0 / sqrt(var + 1e-5));
    g_scale[c] = sc;
    g_shift[c] = beta[c] - (float)mean * sc;
}

// ---------------- split x*scale into bf16 hi/lo -----------------------------
__global__ void split_x_kernel(const float4* __restrict__ x4) {
    size_t i = (size_t)blockIdx.x * blockDim.x + threadIdx.x;
    float4 v = x4[i];
    int c = (int)(i % 192) * 4;
    v.x *= g_scale[c + 0]; v.y *= g_scale[c + 1];
    v.z *= g_scale[c + 2]; v.w *= g_scale[c + 3];
    __nv_bfloat16 h0 = __float2bfloat16(v.x);
    __nv_bfloat16 h1 = __float2bfloat16(v.y);
    __nv_bfloat16 h2 = __float2bfloat16(v.z);
    __nv_bfloat16 h3 = __float2bfloat16(v.w);
    __nv_bfloat16 l0 = __float2bfloat16(v.x - __bfloat162float(h0));
    __nv_bfloat16 l1 = __float2bfloat16(v.y - __bfloat162float(h1));
    __nv_bfloat16 l2 = __float2bfloat16(v.z - __bfloat162float(h2));
    __nv_bfloat16 l3 = __float2bfloat16(v.w - __bfloat162float(h3));
    __nv_bfloat162* ph = (__nv_bfloat162*)g_xh;
    __nv_bfloat162* pl = (__nv_bfloat162*)g_xl;
    ph[i * 2 + 0] = __halves2bfloat162(h0, h1);
    ph[i * 2 + 1] = __halves2bfloat162(h2, h3);
    pl[i * 2 + 0] = __halves2bfloat162(l0, l1);
    pl[i * 2 + 1] = __halves2bfloat162(l2, l3);
}

// ---------------- weight repack: rows n = j*3+g (g in {i,g,o}), hi/lo split --
template <int K, bool L0>
__global__ void repackW_kernel(const float* __restrict__ w) {
    __nv_bfloat16* wh = L0 ? g_W0h : g_W1h;
    __nv_bfloat16* wl = L0 ? g_W0l : g_W1l;
    int idx = blockIdx.x * blockDim.x + threadIdx.x;
    if (idx >= 1536 * K) return;
    int d = idx % K;
    int n = idx / K;
    int g = n % 3, j = n / 3;
    int dir = j >> 8, jj = j & 255;
    int grow = (g == 0) ? jj : (g == 1 ? 512 + jj : 768 + jj);
    float v = w[(size_t)(dir * 1024 + grow) * K + d];
    __nv_bfloat16 h = __float2bfloat16(v);
    wh[idx] = h;
    wl[idx] = __float2bfloat16(v - __bfloat162float(h));
}

__global__ void gconst0_kernel(const float* __restrict__ w,
                               const float* __restrict__ bih,
                               const float* __restrict__ bhh) {
    int warpId = (blockIdx.x * blockDim.x + threadIdx.x) >> 5;
    int lane = threadIdx.x & 31;
    if (warpId >= 1536) return;
    int g = warpId % 3, j = warpId / 3;
    int dir = j >> 8, jj = j & 255;
    int grow = (g == 0) ? jj : (g == 1 ? 512 + jj : 768 + jj);
    const float* wr = w + (size_t)(dir * 1024 + grow) * 768;
    float s = 0.f;
    for (int k = lane; k < 768; k += 32) s += g_shift[k] * wr[k];
    #pragma unroll
    for (int o = 16; o; o >>= 1) s += __shfl_down_sync(0xffffffffu, s, o);
    if (!lane) g_gc0[warpId] = s + bih[dir * 1024 + grow] + bhh[dir * 1024 + grow];
}

__global__ void gconst1_kernel(const float* __restrict__ bih,
                               const float* __restrict__ bhh) {
    int n = blockIdx.x * blockDim.x + threadIdx.x;
    if (n >= 1536) return;
    int g = n % 3, j = n / 3;
    int dir = j >> 8, jj = j & 255;
    int grow = (g == 0) ? jj : (g == 1 ? 512 + jj : 768 + jj);
    g_gc1[n] = bih[dir * 1024 + grow] + bhh[dir * 1024 + grow];
}

// ---------------- HMMA GEMM + fused LSTM epilogue ---------------------------
// CTA 128 rows x 192 gate cols, 512 threads = 16 warps (4M x 4N), warp 32x48.
// bf16x3: acc += Ah*Bh + Ah*Bl + Al*Bh. 3-stage cp.async pipeline, 32-k chunks.
// Stage layout (bf16, row stride 40 elem = 80B): Ah 128x80B=10240, Al +10240,
// Bh +20480 (192x80B=15360), Bl +35840. STAGE=51200, 3 stages = 153600.
#define STAGE   51200
#define OFF_AL  10240
#define OFF_BH  20480
#define OFF_BL  35840
#define SMEM_TC (3 * STAGE)

template <int K, bool L0>
__global__ void __launch_bounds__(512, 1) gemm_lstm_hmma() {
    constexpr int NCH = K / 32;
    const __nv_bfloat16* __restrict__ Ah = L0 ? g_xh : g_h1h;
    const __nv_bfloat16* __restrict__ Al = L0 ? g_xl : g_h1l;
    const __nv_bfloat16* __restrict__ Bh = L0 ? g_W0h : g_W1h;
    const __nv_bfloat16* __restrict__ Bl = L0 ? g_W0l : g_W1l;
    const float* __restrict__ gc = L0 ? g_gc0 : g_gc1;

    extern __shared__ char smem_raw[];
    const uint32_t sb = smem_u32(smem_raw);

    const int tid = threadIdx.x;
    const int wid = tid >> 5, lane = tid & 31;
    const int m0 = blockIdx.y * 128;
    const int n0 = blockIdx.x * 192;

    // ---- chunk loader: 32 k-elements into stage st ----
    auto load_chunk = [&](int kt, int st) {
        uint32_t s = sb + st * STAGE;
        {   // A: 128 rows x 4 x16B, exactly 512 transfers per matrix
            int r = tid >> 2, q = tid & 3;
            uint32_t d = s + r * 80 + q * 16;
            size_t go = (size_t)(m0 + r) * K + kt + q * 8;
            cpasync16(d, Ah + go);
            cpasync16(d + OFF_AL, Al + go);
        }
        #pragma unroll
        for (int i = 0; i < 2; ++i) {   // B: 192 rows x 4 x16B = 768 transfers
            int idx = tid + i * 512;
            if (idx < 768) {
                int r = idx >> 2, q = idx & 3;
                uint32_t d = s + OFF_BH + r * 80 + q * 16;
                size_t go = (size_t)(n0 + r) * K + kt + q * 8;
                cpasync16(d, Bh + go);
                cpasync16(d + (OFF_BL - OFF_BH), Bl + go);
            }
        }
        CP_COMMIT();
    };

    // warp tiling
    const int wm = (wid & 3) * 32;
    const int wn = (wid >> 2) * 48;

    // ldmatrix per-lane selectors
    const int msel   = lane >> 3;
    const int arow_f = (msel & 1) * 8 + (lane & 7);
    const int akoff  = (msel >> 1) * 8;
    const int brow_f = (msel >> 1) * 8 + (lane & 7);
    const int bkoff  = (msel & 1) * 8;

    float acc[2][6][4];
    #pragma unroll
    for (int mt = 0; mt < 2; mt++)
        #pragma unroll
        for (int nb = 0; nb < 6; nb++)
            #pragma unroll
            for (int r = 0; r < 4; r++) acc[mt][nb][r] = 0.f;

    load_chunk(0, 0);
    load_chunk(32, 1);
    load_chunk(64, 2);

    #pragma unroll 1
    for (int c = 0; c < NCH; ++c) {
        asm volatile("cp.async.wait_group 2;" ::: "memory");
        __syncthreads();
        const uint32_t s = sb + (c % 3) * STAGE;

        #pragma unroll
        for (int ks = 0; ks < 32; ks += 16) {
            uint32_t ah[2][4], al[2][4], bh[6][2], bl[6][2];
            #pragma unroll
            for (int mt = 0; mt < 2; mt++) {
                uint32_t ad = s + (wm + mt * 16 + arow_f) * 80 + (ks + akoff) * 2;
                ldsm4(ah[mt][0], ah[mt][1], ah[mt][2], ah[mt][3], ad);
                ldsm4(al[mt][0], al[mt][1], al[mt][2], al[mt][3], ad + OFF_AL);
            }
            #pragma unroll
            for (int p = 0; p < 3; p++) {
                uint32_t bd = s + OFF_BH + (wn + p * 16 + brow_f) * 80 + (ks + bkoff) * 2;
                ldsm4(bh[2 * p][0], bh[2 * p][1], bh[2 * p + 1][0], bh[2 * p + 1][1], bd);
                ldsm4(bl[2 * p][0], bl[2 * p][1], bl[2 * p + 1][0], bl[2 * p + 1][1],
                      bd + (OFF_BL - OFF_BH));
            }
            #pragma unroll
            for (int mt = 0; mt < 2; mt++)
                #pragma unroll
                for (int nb = 0; nb < 6; nb++) {
                    mma16816(acc[mt][nb], ah[mt], bh[nb]);
                    mma16816(acc[mt][nb], ah[mt], bl[nb]);
                    mma16816(acc[mt][nb], al[mt], bh[nb]);
                }
        }
        __syncthreads();
        if (c + 3 < NCH) load_chunk((c + 3) * 32, c % 3);
        else             CP_COMMIT();          // empty group keeps wait count uniform
    }

    // ---- fused epilogue: stage accs, recombine gate triples -----------------
    float* sC = (float*)smem_raw;              // [128][200] floats = 102400B
    #pragma unroll
    for (int mt = 0; mt < 2; mt++)
        #pragma unroll
        for (int nb = 0; nb < 6; nb++) {
            int r = wm + mt * 16 + (lane >> 2);
            int cc = wn + nb * 8 + (lane & 3) * 2;
            sC[r * 200 + cc]           = acc[mt][nb][0];
            sC[r * 200 + cc + 1]       = acc[mt][nb][1];
            sC[(r + 8) * 200 + cc]     = acc[mt][nb][2];
            sC[(r + 8) * 200 + cc + 1] = acc[mt][nb][3];
        }
    __syncthreads();

    const int cb = blockIdx.x * 64;
    #pragma unroll
    for (int t = 0; t < 16; t++) {
        int idx = t * 512 + tid;               // 128 rows x 64 h-units
        int r = idx >> 6, j = idx & 63;
        float iv = sC[r * 200 + 3 * j + 0] + gc[n0 + 3 * j + 0];
        float gv = sC[r * 200 + 3 * j + 1] + gc[n0 + 3 * j + 1];
        float ov = sC[r * 200 + 3 * j + 2] + gc[n0 + 3 * j + 2];
        float cv = (1.f / (1.f + expf(-iv))) * tanhf(gv);
        float hv = (1.f / (1.f + expf(-ov))) * tanhf(cv);
        size_t o = (size_t)(m0 + r) * 512 + cb + j;
        if (L0) {
            __nv_bfloat16 hh = __float2bfloat16(hv);
            g_h1h[o] = hh;
            g_h1l[o] = __float2bfloat16(hv - __bfloat162float(hh));
        } else {
            g_h2[o] = hv;
        }
    }
}

// ---------------- FC ----------------
__global__ __launch_bounds__(256)
void fc_kernel(const float* __restrict__ fcw, const float* __restrict__ fcb,
               float* __restrict__ e, int nrows) {
    __shared__ float w0[512], w1[512];
    for (int i = threadIdx.x; i < 512; i += blockDim.x) {
        w0[i] = fcw[i];
        w1[i] = fcw[512 + i];
    }
    __syncthreads();
    int warp = (int)((blockIdx.x * (size_t)blockDim.x + threadIdx.x) >> 5);
    int lane = threadIdx.x & 31;
    if (warp >= nrows) return;
    const float* h = g_h2 + (size_t)warp * 512;
    float s0 = 0.f, s1 = 0.f;
    #pragma unroll
    for (int k = lane * 4; k < 512; k += 128) {
        float4 hv = *(const float4*)(h + k);
        s0 += hv.x * w0[k] + hv.y * w0[k + 1] + hv.z * w0[k + 2] + hv.w * w0[k + 3];
        s1 += hv.x * w1[k] + hv.y * w1[k + 1] + hv.z * w1[k + 2] + hv.w * w1[k + 3];
    }
    #pragma unroll
    for (int o = 16; o; o >>= 1) {
        s0 += __shfl_down_sync(0xffffffffu, s0, o);
        s1 += __shfl_down_sync(0xffffffffu, s1, o);
    }
    if (!lane) {
        e[(size_t)warp * 2 + 0] = s0 + fcb[0];
        e[(size_t)warp * 2 + 1] = s1 + fcb[1];
    }
}

// ---------------- CRF NLL ----------------
__device__ __forceinline__ double lse2(double a, double b) {
    double m = fmax(a, b), n = fmin(a, b);
    return m + log1p(exp(n - m));
}

__global__ __launch_bounds__(1024)
void crf_kernel(const float* __restrict__ e, const int* __restrict__ tags,
                const float* __restrict__ startv, const float* __restrict__ endv,
                const float* __restrict__ trans, float* __restrict__ loss_out, int N) {
    __shared__ double sP[1024][4];
    __shared__ double sNum[1024];
    int tid = threadIdx.x;
    const double T00 = trans[0], T01 = trans[1], T10 = trans[2], T11 = trans[3];
    const double NEG = -1e30;

    int chunk = (N + 1023) >> 10;
    long s0 = (long)tid * chunk;
    long s1 = s0 + chunk; if (s1 > N) s1 = N;

    double P00 = 0.0, P01 = NEG, P10 = NEG, P11 = 0.0;
    double np = 0.0;
    for (long n = s0; n < s1; ++n) {
        int t = tags[n];
        np += (double)e[n * 2 + t];
        if (n >= 1) {
            int tp = tags[n - 1];
            np += (tp == 0) ? (t == 0 ? T00 : T01) : (t == 0 ? T10 : T11);
            double e0 = (double)e[n * 2 + 0];
            double e1 = (double)e[n * 2 + 1];
            double n00 = lse2(P00 + T00, P01 + T10) + e0;
            double n01 = lse2(P00 + T01, P01 + T11) + e1;
            double n10 = lse2(P10 + T00, P11 + T10) + e0;
            double n11 = lse2(P10 + T01, P11 + T11) + e1;
            P00 = n00; P01 = n01; P10 = n10; P11 = n11;
        }
    }
    sP[tid][0] = P00; sP[tid][1] = P01; sP[tid][2] = P10; sP[tid][3] = P11;
    sNum[tid] = np;
    __syncthreads();

    for (int nthr = 1024; nthr > 1; nthr >>= 1) {
        int half = nthr >> 1;
        double a0, a1, a2, a3, b0, b1, b2, b3, nn;
        bool act = tid < half;
        if (act) {
            a0 = sP[2 * tid][0];     a1 = sP[2 * tid][1];
            a2 = sP[2 * tid][2];     a3 = sP[2 * tid][3];
            b0 = sP[2 * tid + 1][0]; b1 = sP[2 * tid + 1][1];
            b2 = sP[2 * tid + 1][2]; b3 = sP[2 * tid + 1][3];
            nn = sNum[2 * tid] + sNum[2 * tid + 1];
        }
        __syncthreads();
        if (act) {
            sP[tid][0] = lse2(a0 + b0, a1 + b2);
            sP[tid][1] = lse2(a0 + b1, a1 + b3);
            sP[tid][2] = lse2(a2 + b0, a3 + b2);
            sP[tid][3] = lse2(a2 + b1, a3 + b3);
            sNum[tid] = nn;
        }
        __syncthreads();
    }

    if (tid == 0) {
        double num = sNum[0] + (double)startv[tags[0]] + (double)endv[tags[N - 1]];
        double a0 = (double)startv[0] + (double)e[0];
        double a1 = (double)startv[1] + (double)e[1];
        double f0 = lse2(a0 + sP[0][0], a1 + sP[0][2]);
        double f1 = lse2(a0 + sP[0][1], a1 + sP[0][3]);
        double den = lse2(f0 + (double)endv[0], f1 + (double)endv[1]);
        loss_out[0] = (float)(den - num);
    }
}

// ---------------- launch ----------------
extern "C" void kernel_launch(void* const* d_in, const int* in_sizes, int n_in,
                              void* d_out, int out_size) {
    const float* x        = (const float*)d_in[0];
    const float* gamma    = (const float*)d_in[1];
    const float* beta     = (const float*)d_in[2];
    const float* w_ih_l0  = (const float*)d_in[3];
    const float* b_ih_l0  = (const float*)d_in[5];
    const float* b_hh_l0  = (const float*)d_in[6];
    const float* w_ih_l1  = (const float*)d_in[7];
    const float* b_ih_l1  = (const float*)d_in[9];
    const float* b_hh_l1  = (const float*)d_in[10];
    const float* fc_w     = (const float*)d_in[11];
    const float* fc_b     = (const float*)d_in[12];
    const float* crf_start= (const float*)d_in[13];
    const float* crf_end  = (const float*)d_in[14];
    const float* crf_trans= (const float*)d_in[15];
    const int*   labels   = (const int*)d_in[16];

    int N = in_sizes[0] / 768;      // 65536
    float* out = (float*)d_out;
    float* e = out + 1;

    cudaFuncSetAttribute((const void*)gemm_lstm_hmma<768, true>,
                         cudaFuncAttributeMaxDynamicSharedMemorySize, SMEM_TC);
    cudaFuncSetAttribute((const void*)gemm_lstm_hmma<512, false>,
                         cudaFuncAttributeMaxDynamicSharedMemorySize, SMEM_TC);

    // launch order puts gemm L0 at index 5 for ncu -s 5 -c 1
    int rpb = (N + 127) / 128;                 // <=128 blocks
    int nblk = (N + rpb - 1) / rpb;
    stats_kernel<<<nblk, 768>>>(x, rpb, N);                                   // 0
    prep_kernel<<<1, 768>>>(gamma, beta, N, nblk);                            // 1
    split_x_kernel<<<(N * 768 / 4 + 255) / 256, 256>>>((const float4*)x);     // 2
    repackW_kernel<768, true ><<<(1536 * 768 + 255) / 256, 256>>>(w_ih_l0);   // 3
    gconst0_kernel<<<(1536 * 32 + 255) / 256, 256>>>(w_ih_l0, b_ih_l0, b_hh_l0); // 4

    dim3 gg(8, N / 128);
    gemm_lstm_hmma<768, true ><<<gg, 512, SMEM_TC>>>();                       // 5

    repackW_kernel<512, false><<<(1536 * 512 + 255) / 256, 256>>>(w_ih_l1);   // 6
    gconst1_kernel<<<(1536 + 255) / 256, 256>>>(b_ih_l1, b_hh_l1);            // 7
    gemm_lstm_hmma<512, false><<<gg, 512, SMEM_TC>>>();                       // 8

    fc_kernel<<<(N / 8), 256>>>(fc_w, fc_b, e, N);                            // 9
    crf_kernel<<<1, 1024>>>(e, labels, crf_start, crf_end, crf_trans, out, N);// 10
}

// round 6
// speedup vs baseline: 2.5089x; 2.5089x over previous
#include <cuda_runtime.h>
#include <cuda_bf16.h>
#include <math.h>
#include <stdint.h>

#define NROWS 65536

// ---------------- scratch (device globals; no allocation allowed) ----------
__device__ float  g_psum[128 * 768];
__device__ float  g_psumsq[128 * 768];
__device__ float  g_scale[768];
__device__ float  g_shift[768];
__device__ __nv_bfloat16 g_xh[(size_t)NROWS * 768];
__device__ __nv_bfloat16 g_xl[(size_t)NROWS * 768];
__device__ __nv_bfloat16 g_W0h[1536 * 768];
__device__ __nv_bfloat16 g_W0l[1536 * 768];
__device__ __nv_bfloat16 g_W1h[1536 * 512];
__device__ __nv_bfloat16 g_W1l[1536 * 512];
__device__ __nv_bfloat16 g_h1h[(size_t)NROWS * 512];
__device__ __nv_bfloat16 g_h1l[(size_t)NROWS * 512];
__device__ float g_h2[(size_t)NROWS * 512];
__device__ float g_gc0[1536];
__device__ float g_gc1[1536];
__device__ double g_crfP[256][4];
__device__ double g_crfN[256];

// ---------------- helpers ----------------
__device__ __forceinline__ uint32_t smem_u32(const void* p) {
    uint32_t a;
    asm("{ .reg .u64 t; cvta.to.shared.u64 t, %1; cvt.u32.u64 %0, t; }" : "=r"(a) : "l"(p));
    return a;
}
__device__ __forceinline__ void cpasync16(uint32_t dst, const void* src) {
    asm volatile("cp.async.cg.shared.global [%0], [%1], 16;" :: "r"(dst), "l"(src));
}
#define CP_COMMIT() asm volatile("cp.async.commit_group;")

__device__ __forceinline__ void ldsm4(uint32_t& r0, uint32_t& r1, uint32_t& r2,
                                      uint32_t& r3, uint32_t addr) {
    asm volatile("ldmatrix.sync.aligned.m8n8.x4.shared.b16 {%0,%1,%2,%3}, [%4];"
                 : "=r"(r0), "=r"(r1), "=r"(r2), "=r"(r3) : "r"(addr));
}
__device__ __forceinline__ void ldsm2(uint32_t& r0, uint32_t& r1, uint32_t addr) {
    asm volatile("ldmatrix.sync.aligned.m8n8.x2.shared.b16 {%0,%1}, [%2];"
                 : "=r"(r0), "=r"(r1) : "r"(addr));
}
__device__ __forceinline__ void mma16816(float* c, const uint32_t* a, const uint32_t* b) {
    asm volatile("mma.sync.aligned.m16n8k16.row.col.f32.bf16.bf16.f32 "
                 "{%0,%1,%2,%3}, {%4,%5,%6,%7}, {%8,%9}, {%0,%1,%2,%3};"
                 : "+f"(c[0]), "+f"(c[1]), "+f"(c[2]), "+f"(c[3])
                 : "r"(a[0]), "r"(a[1]), "r"(a[2]), "r"(a[3]), "r"(b[0]), "r"(b[1]));
}

// ---------------- BN stats (per-block partials) -----------------------------
__global__ void stats_kernel(const float* __restrict__ x, int rowsPerBlock, int nrows) {
    int c = threadIdx.x;
    int b = blockIdx.x;
    long r0 = (long)b * rowsPerBlock;
    float s = 0.f, s2 = 0.f;
    for (int r = 0; r < rowsPerBlock; ++r) {
        long row = r0 + r;
        if (row < nrows) {
            float v = x[row * 768 + c];
            s += v; s2 += v * v;
        }
    }
    g_psum[b * 768 + c] = s;
    g_psumsq[b * 768 + c] = s2;
}

__global__ void prep_kernel(const float* __restrict__ gamma,
                            const float* __restrict__ beta, int nrows, int nblk) {
    int c = threadIdx.x;
    double s = 0.0, s2 = 0.0;
    for (int b = 0; b < nblk; ++b) {
        s  += (double)g_psum[b * 768 + c];
        s2 += (double)g_psumsq[b * 768 + c];
    }
    double mean = s / (double)nrows;
    double var  = s2 / (double)nrows - mean * mean;
    float sc = gamma[c] * (float)(1.0 / sqrt(var + 1e-5));
    g_scale[c] = sc;
    g_shift[c] = beta[c] - (float)mean * sc;
}

// ------------- merged L0 prep: split_x + repackW0 + gconst0 ------------------
// grid = nsplit + 4608 + 192 blocks of 256 threads, branch on blockIdx.x
__global__ void prep_all_l0(const float4* __restrict__ x4,
                            const float* __restrict__ w,
                            const float* __restrict__ bih,
                            const float* __restrict__ bhh,
                            int nsplit) {
    int bid = blockIdx.x;
    int tid = threadIdx.x;
    if (bid < nsplit) {
        size_t i = (size_t)bid * 256 + tid;
        float4 v = x4[i];
        int c = (int)(i % 192) * 4;
        v.x *= g_scale[c + 0]; v.y *= g_scale[c + 1];
        v.z *= g_scale[c + 2]; v.w *= g_scale[c + 3];
        __nv_bfloat16 h0 = __float2bfloat16(v.x);
        __nv_bfloat16 h1 = __float2bfloat16(v.y);
        __nv_bfloat16 h2 = __float2bfloat16(v.z);
        __nv_bfloat16 h3 = __float2bfloat16(v.w);
        __nv_bfloat16 l0 = __float2bfloat16(v.x - __bfloat162float(h0));
        __nv_bfloat16 l1 = __float2bfloat16(v.y - __bfloat162float(h1));
        __nv_bfloat16 l2 = __float2bfloat16(v.z - __bfloat162float(h2));
        __nv_bfloat16 l3 = __float2bfloat16(v.w - __bfloat162float(h3));
        __nv_bfloat162* ph = (__nv_bfloat162*)g_xh;
        __nv_bfloat162* pl = (__nv_bfloat162*)g_xl;
        ph[i * 2 + 0] = __halves2bfloat162(h0, h1);
        ph[i * 2 + 1] = __halves2bfloat162(h2, h3);
        pl[i * 2 + 0] = __halves2bfloat162(l0, l1);
        pl[i * 2 + 1] = __halves2bfloat162(l2, l3);
    } else if (bid < nsplit + 4608) {
        int idx = (bid - nsplit) * 256 + tid;      // < 1536*768
        int d = idx % 768;
        int n = idx / 768;
        int g = n % 3, j = n / 3;
        int dir = j >> 8, jj = j & 255;
        int grow = (g == 0) ? jj : (g == 1 ? 512 + jj : 768 + jj);
        float v = w[(size_t)(dir * 1024 + grow) * 768 + d];
        __nv_bfloat16 h = __float2bfloat16(v);
        g_W0h[idx] = h;
        g_W0l[idx] = __float2bfloat16(v - __bfloat162float(h));
    } else {
        int warpId = (bid - nsplit - 4608) * 8 + (tid >> 5);   // < 1536
        int lane = tid & 31;
        int g = warpId % 3, j = warpId / 3;
        int dir = j >> 8, jj = j & 255;
        int grow = (g == 0) ? jj : (g == 1 ? 512 + jj : 768 + jj);
        const float* wr = w + (size_t)(dir * 1024 + grow) * 768;
        float s = 0.f;
        for (int k = lane; k < 768; k += 32) s += g_shift[k] * wr[k];
        #pragma unroll
        for (int o = 16; o; o >>= 1) s += __shfl_down_sync(0xffffffffu, s, o);
        if (!lane) g_gc0[warpId] = s + bih[dir * 1024 + grow] + bhh[dir * 1024 + grow];
    }
}

// ------------- merged L1 prep: repackW1 + gconst1 ----------------------------
__global__ void prep_l1(const float* __restrict__ w,
                        const float* __restrict__ bih,
                        const float* __restrict__ bhh) {
    int bid = blockIdx.x;
    int tid = threadIdx.x;
    if (bid < 3072) {
        int idx = bid * 256 + tid;                 // < 1536*512
        int d = idx % 512;
        int n = idx / 512;
        int g = n % 3, j = n / 3;
        int dir = j >> 8, jj = j & 255;
        int grow = (g == 0) ? jj : (g == 1 ? 512 + jj : 768 + jj);
        float v = w[(size_t)(dir * 1024 + grow) * 512 + d];
        __nv_bfloat16 h = __float2bfloat16(v);
        g_W1h[idx] = h;
        g_W1l[idx] = __float2bfloat16(v - __bfloat162float(h));
    } else {
        int n = (bid - 3072) * 256 + tid;
        if (n >= 1536) return;
        int g = n % 3, j = n / 3;
        int dir = j >> 8, jj = j & 255;
        int grow = (g == 0) ? jj : (g == 1 ? 512 + jj : 768 + jj);
        g_gc1[n] = bih[dir * 1024 + grow] + bhh[dir * 1024 + grow];
    }
}

// ---------------- HMMA GEMM + fused LSTM epilogue (R3 config) ---------------
// CTA 128 x 96 h-units... cols: 128 rows x 192 gate cols? No: 128 x 96 gate
// cols? -- R3: CTA 128 rows x 96 gate cols... (grid 16 x N/128), warp 64x24.
#define GBUF   35840
#define OFF_AL 10240
#define OFF_BH 20480
#define OFF_BL 28160

template <bool L0>
__global__ void __launch_bounds__(256) gemm_lstm_tc() {
    constexpr int K = L0 ? 768 : 512;
    constexpr int NCH = K / 32;
    const __nv_bfloat16* __restrict__ Ah = L0 ? g_xh : g_h1h;
    const __nv_bfloat16* __restrict__ Al = L0 ? g_xl : g_h1l;
    const __nv_bfloat16* __restrict__ Bh = L0 ? g_W0h : g_W1h;
    const __nv_bfloat16* __restrict__ Bl = L0 ? g_W0l : g_W1l;
    const float* __restrict__ gc = L0 ? g_gc0 : g_gc1;

    extern __shared__ char smem[];
    uint32_t sbase = (uint32_t)__cvta_generic_to_shared(smem);

    const int tid = threadIdx.x;
    const int m0 = blockIdx.y * 128;
    const int n0 = blockIdx.x * 96;

    auto issue = [&](int kt, int b) {
        uint32_t sA = sbase + b * GBUF;
        #pragma unroll
        for (int it = 0; it < 2; ++it) {
            int idx = tid + it * 256;
            int r = idx >> 2, q = idx & 3;
            uint32_t d = sA + r * 80 + q * 16;
            const size_t go = (size_t)(m0 + r) * K + kt + q * 8;
            cpasync16(d, Ah + go);
            cpasync16(d + OFF_AL, Al + go);
        }
        {
            int r = tid >> 2, q = tid & 3;
            uint32_t d = sA + OFF_BH + r * 80 + q * 16;
            const size_t go = (size_t)(n0 + r) * K + kt + q * 8;
            cpasync16(d, Bh + go);
            cpasync16(d + (OFF_BL - OFF_BH), Bl + go);
            if (tid < 128) {
                int r2 = 64 + (tid >> 2), q2 = tid & 3;
                uint32_t d2 = sA + OFF_BH + r2 * 80 + q2 * 16;
                const size_t go2 = (size_t)(n0 + r2) * K + kt + q2 * 8;
                cpasync16(d2, Bh + go2);
                cpasync16(d2 + (OFF_BL - OFF_BH), Bl + go2);
            }
        }
        CP_COMMIT();
    };

    const int lane = tid & 31, wid = tid >> 5;
    const int wm = (wid & 1) * 64;
    const int wn = (wid >> 1) * 24;

    const int msel   = lane >> 3;
    const int arow_f = (msel & 1) * 8 + (lane & 7);
    const int akoff  = (msel >> 1) * 8;
    const int brow_f = (msel >> 1) * 8 + (lane & 7);
    const int bkoff  = (msel & 1) * 8;
    const int l2     = lane & 15;
    const int b2row  = 16 + (l2 & 7);
    const int b2koff = ((l2 >> 3) & 1) * 8;

    float acc[4][3][4];
    #pragma unroll
    for (int mt = 0; mt < 4; mt++)
        #pragma unroll
        for (int nb = 0; nb < 3; nb++)
            #pragma unroll
            for (int r = 0; r < 4; r++) acc[mt][nb][r] = 0.f;

    issue(0, 0);

    #pragma unroll 1
    for (int c = 0; c < NCH; ++c) {
        if (c + 1 < NCH) {
            issue((c + 1) * 32, (c + 1) & 1);
            asm volatile("cp.async.wait_group 1;");
        } else {
            asm volatile("cp.async.wait_group 0;");
        }
        __syncthreads();
        uint32_t sA = sbase + (c & 1) * GBUF;

        #pragma unroll
        for (int ks = 0; ks < 32; ks += 16) {
            uint32_t ah[4][4], al[4][4], bh[3][2], bl[3][2];
            #pragma unroll
            for (int mt = 0; mt < 4; mt++) {
                uint32_t ad = sA + (wm + mt * 16 + arow_f) * 80 + (ks + akoff) * 2;
                ldsm4(ah[mt][0], ah[mt][1], ah[mt][2], ah[mt][3], ad);
                ldsm4(al[mt][0], al[mt][1], al[mt][2], al[mt][3], ad + OFF_AL);
            }
            {
                uint32_t bd = sA + OFF_BH + (wn + brow_f) * 80 + (ks + bkoff) * 2;
                ldsm4(bh[0][0], bh[0][1], bh[1][0], bh[1][1], bd);
                ldsm4(bl[0][0], bl[0][1], bl[1][0], bl[1][1], bd + (OFF_BL - OFF_BH));
                uint32_t bd2 = sA + OFF_BH + (wn + b2row) * 80 + (ks + b2koff) * 2;
                ldsm2(bh[2][0], bh[2][1], bd2);
                ldsm2(bl[2][0], bl[2][1], bd2 + (OFF_BL - OFF_BH));
            }
            #pragma unroll
            for (int mt = 0; mt < 4; mt++)
                #pragma unroll
                for (int nb = 0; nb < 3; nb++) {
                    mma16816(acc[mt][nb], ah[mt], bh[nb]);
                    mma16816(acc[mt][nb], ah[mt], bl[nb]);
                    mma16816(acc[mt][nb], al[mt], bh[nb]);
                }
        }
        __syncthreads();
    }

    float* sC = (float*)smem;
    #pragma unroll
    for (int mt = 0; mt < 4; mt++)
        #pragma unroll
        for (int nb = 0; nb < 3; nb++) {
            int r = wm + mt * 16 + (lane >> 2);
            int cc = wn + nb * 8 + (lane & 3) * 2;
            sC[r * 100 + cc]           = acc[mt][nb][0];
            sC[r * 100 + cc + 1]       = acc[mt][nb][1];
            sC[(r + 8) * 100 + cc]     = acc[mt][nb][2];
            sC[(r + 8) * 100 + cc + 1] = acc[mt][nb][3];
        }
    __syncthreads();

    #pragma unroll
    for (int t = 0; t < 16; t++) {
        int idx = t * 256 + tid;
        int r = idx >> 5, j = idx & 31;
        float iv = sC[r * 100 + 3 * j + 0] + gc[n0 + 3 * j + 0];
        float gv = sC[r * 100 + 3 * j + 1] + gc[n0 + 3 * j + 1];
        float ov = sC[r * 100 + 3 * j + 2] + gc[n0 + 3 * j + 2];
        float cv = (1.f / (1.f + expf(-iv))) * tanhf(gv);
        float hv = (1.f / (1.f + expf(-ov))) * tanhf(cv);
        size_t o = (size_t)(m0 + r) * 512 + (size_t)(n0 / 3 + j);
        if (L0) {
            __nv_bfloat16 hh = __float2bfloat16(hv);
            g_h1h[o] = hh;
            g_h1l[o] = __float2bfloat16(hv - __bfloat162float(hh));
        } else {
            g_h2[o] = hv;
        }
    }
}

// ---------------- FC ----------------
__global__ __launch_bounds__(256)
void fc_kernel(const float* __restrict__ fcw, const float* __restrict__ fcb,
               float* __restrict__ e, int nrows) {
    __shared__ float w0[512], w1[512];
    for (int i = threadIdx.x; i < 512; i += blockDim.x) {
        w0[i] = fcw[i];
        w1[i] = fcw[512 + i];
    }
    __syncthreads();
    int warp = (int)((blockIdx.x * (size_t)blockDim.x + threadIdx.x) >> 5);
    int lane = threadIdx.x & 31;
    if (warp >= nrows) return;
    const float* h = g_h2 + (size_t)warp * 512;
    float s0 = 0.f, s1 = 0.f;
    #pragma unroll
    for (int k = lane * 4; k < 512; k += 128) {
        float4 hv = *(const float4*)(h + k);
        s0 += hv.x * w0[k] + hv.y * w0[k + 1] + hv.z * w0[k + 2] + hv.w * w0[k + 3];
        s1 += hv.x * w1[k] + hv.y * w1[k + 1] + hv.z * w1[k + 2] + hv.w * w1[k + 3];
    }
    #pragma unroll
    for (int o = 16; o; o >>= 1) {
        s0 += __shfl_down_sync(0xffffffffu, s0, o);
        s1 += __shfl_down_sync(0xffffffffu, s1, o);
    }
    if (!lane) {
        e[(size_t)warp * 2 + 0] = s0 + fcb[0];
        e[(size_t)warp * 2 + 1] = s1 + fcb[1];
    }
}

// ---------------- CRF NLL: parallel log-semiring reduce ----------------------
__device__ __forceinline__ double lse2(double a, double b) {
    double m = fmax(a, b), n = fmin(a, b);
    return m + log1p(exp(n - m));
}

// part: each thread = one sequence element; block tree-composes 256 of them.
__global__ __launch_bounds__(256)
void crf_part(const float* __restrict__ e, const int* __restrict__ tags,
              const float* __restrict__ trans, int N) {
    __shared__ double sP[256][4];
    __shared__ double sN[256];
    const int t = threadIdx.x;
    const long n = (long)blockIdx.x * 256 + t;
    const double T00 = trans[0], T01 = trans[1], T10 = trans[2], T11 = trans[3];
    const double NEG = -1e30;

    double m00 = 0.0, m01 = NEG, m10 = NEG, m11 = 0.0;   // identity
    double np = 0.0;
    if (n < N) {
        int tg = tags[n];
        np = (double)e[n * 2 + tg];
        if (n >= 1) {
            int tp = tags[n - 1];
            np += (tp == 0) ? (tg == 0 ? T00 : T01) : (tg == 0 ? T10 : T11);
            double e0 = (double)e[n * 2 + 0];
            double e1 = (double)e[n * 2 + 1];
            m00 = T00 + e0; m01 = T01 + e1;
            m10 = T10 + e0; m11 = T11 + e1;
        }
    }
    sP[t][0] = m00; sP[t][1] = m01; sP[t][2] = m10; sP[t][3] = m11;
    sN[t] = np;
    __syncthreads();

    for (int half = 128; half >= 1; half >>= 1) {
        double a0, a1, a2, a3, b0, b1, b2, b3, nn;
        bool act = t < half;
        if (act) {
            a0 = sP[2 * t][0];     a1 = sP[2 * t][1];
            a2 = sP[2 * t][2];     a3 = sP[2 * t][3];
            b0 = sP[2 * t + 1][0]; b1 = sP[2 * t + 1][1];
            b2 = sP[2 * t + 1][2]; b3 = sP[2 * t + 1][3];
            nn = sN[2 * t] + sN[2 * t + 1];
        }
        __syncthreads();
        if (act) {
            sP[t][0] = lse2(a0 + b0, a1 + b2);
            sP[t][1] = lse2(a0 + b1, a1 + b3);
            sP[t][2] = lse2(a2 + b0, a3 + b2);
            sP[t][3] = lse2(a2 + b1, a3 + b3);
            sN[t] = nn;
        }
        __syncthreads();
    }
    if (t == 0) {
        g_crfP[blockIdx.x][0] = sP[0][0];
        g_crfP[blockIdx.x][1] = sP[0][1];
        g_crfP[blockIdx.x][2] = sP[0][2];
        g_crfP[blockIdx.x][3] = sP[0][3];
        g_crfN[blockIdx.x] = sN[0];
    }
}

__global__ __launch_bounds__(256)
void crf_comb(const float* __restrict__ e, const int* __restrict__ tags,
              const float* __restrict__ startv, const float* __restrict__ endv,
              float* __restrict__ loss_out, int N, int nb) {
    __shared__ double sP[256][4];
    __shared__ double sN[256];
    const int t = threadIdx.x;
    const double NEG = -1e30;
    if (t < nb) {
        sP[t][0] = g_crfP[t][0]; sP[t][1] = g_crfP[t][1];
        sP[t][2] = g_crfP[t][2]; sP[t][3] = g_crfP[t][3];
        sN[t] = g_crfN[t];
    } else {
        sP[t][0] = 0.0; sP[t][1] = NEG; sP[t][2] = NEG; sP[t][3] = 0.0;
        sN[t] = 0.0;
    }
    __syncthreads();

    for (int half = 128; half >= 1; half >>= 1) {
        double a0, a1, a2, a3, b0, b1, b2, b3, nn;
        bool act = t < half;
        if (act) {
            a0 = sP[2 * t][0];     a1 = sP[2 * t][1];
            a2 = sP[2 * t][2];     a3 = sP[2 * t][3];
            b0 = sP[2 * t + 1][0]; b1 = sP[2 * t + 1][1];
            b2 = sP[2 * t + 1][2]; b3 = sP[2 * t + 1][3];
            nn = sN[2 * t] + sN[2 * t + 1];
        }
        __syncthreads();
        if (act) {
            sP[t][0] = lse2(a0 + b0, a1 + b2);
            sP[t][1] = lse2(a0 + b1, a1 + b3);
            sP[t][2] = lse2(a2 + b0, a3 + b2);
            sP[t][3] = lse2(a2 + b1, a3 + b3);
            sN[t] = nn;
        }
        __syncthreads();
    }

    if (t == 0) {
        double num = sN[0] + (double)startv[tags[0]] + (double)endv[tags[N - 1]];
        double a0 = (double)startv[0] + (double)e[0];
        double a1 = (double)startv[1] + (double)e[1];
        double f0 = lse2(a0 + sP[0][0], a1 + sP[0][2]);
        double f1 = lse2(a0 + sP[0][1], a1 + sP[0][3]);
        double den = lse2(f0 + (double)endv[0], f1 + (double)endv[1]);
        loss_out[0] = (float)(den - num);
    }
}

// ---------------- launch ----------------
extern "C" void kernel_launch(void* const* d_in, const int* in_sizes, int n_in,
                              void* d_out, int out_size) {
    const float* x        = (const float*)d_in[0];
    const float* gamma    = (const float*)d_in[1];
    const float* beta     = (const float*)d_in[2];
    const float* w_ih_l0  = (const float*)d_in[3];
    const float* b_ih_l0  = (const float*)d_in[5];
    const float* b_hh_l0  = (const float*)d_in[6];
    const float* w_ih_l1  = (const float*)d_in[7];
    const float* b_ih_l1  = (const float*)d_in[9];
    const float* b_hh_l1  = (const float*)d_in[10];
    const float* fc_w     = (const float*)d_in[11];
    const float* fc_b     = (const float*)d_in[12];
    const float* crf_start= (const float*)d_in[13];
    const float* crf_end  = (const float*)d_in[14];
    const float* crf_trans= (const float*)d_in[15];
    const int*   labels   = (const int*)d_in[16];

    int N = in_sizes[0] / 768;      // 65536
    float* out = (float*)d_out;
    float* e = out + 1;

    cudaFuncSetAttribute((const void*)gemm_lstm_tc<true>,
                         cudaFuncAttributeMaxDynamicSharedMemorySize, 2 * GBUF);
    cudaFuncSetAttribute((const void*)gemm_lstm_tc<false>,
                         cudaFuncAttributeMaxDynamicSharedMemorySize, 2 * GBUF);

    int rpb = (N + 127) / 128;
    int nblk = (N + rpb - 1) / rpb;
    int nsplit = N * 768 / 4 / 256;                        // 49152

    stats_kernel<<<nblk, 768>>>(x, rpb, N);                                    // 0
    prep_kernel<<<1, 768>>>(gamma, beta, N, nblk);                             // 1
    prep_all_l0<<<nsplit + 4608 + 192, 256>>>((const float4*)x, w_ih_l0,
                                              b_ih_l0, b_hh_l0, nsplit);       // 2
    dim3 gg(16, N / 128);
    gemm_lstm_tc<true ><<<gg, 256, 2 * GBUF>>>();                              // 3  <- ncu
    prep_l1<<<3078, 256>>>(w_ih_l1, b_ih_l1, b_hh_l1);                         // 4
    gemm_lstm_tc<false><<<gg, 256, 2 * GBUF>>>();                              // 5
    fc_kernel<<<(N / 8), 256>>>(fc_w, fc_b, e, N);                             // 6
    crf_part<<<(N + 255) / 256, 256>>>(e, labels, crf_trans, N);               // 7
    crf_comb<<<1, 256>>>(e, labels, crf_start, crf_end, out, N, (N + 255) / 256); // 8
}

// round 8
// speedup vs baseline: 2.5601x; 1.0204x over previous
#include <cuda_runtime.h>
#include <cuda_bf16.h>
#include <math.h>
#include <stdint.h>

#define NROWS 65536

// ---------------- scratch (device globals; no allocation allowed) ----------
__device__ float  g_psum[128 * 768];
__device__ float  g_psumsq[128 * 768];
__device__ float  g_scale[768];
__device__ float  g_shift[768];
__device__ __nv_bfloat16 g_xh[(size_t)NROWS * 768];
__device__ __nv_bfloat16 g_xl[(size_t)NROWS * 768];
__device__ __nv_bfloat16 g_W0h[1536 * 768];
__device__ __nv_bfloat16 g_W0l[1536 * 768];
__device__ __nv_bfloat16 g_W1h[1536 * 512];
__device__ __nv_bfloat16 g_W1l[1536 * 512];
__device__ __nv_bfloat16 g_h1h[(size_t)NROWS * 512];
__device__ __nv_bfloat16 g_h1l[(size_t)NROWS * 512];
__device__ float g_h2[(size_t)NROWS * 512];
__device__ float g_gc0[1536];
__device__ float g_gc1[1536];
__device__ double g_crfP[256][4];
__device__ double g_crfN[256];

// ---------------- helpers ----------------
__device__ __forceinline__ void cpasync16(uint32_t dst, const void* src) {
    asm volatile("cp.async.cg.shared.global [%0], [%1], 16;" :: "r"(dst), "l"(src));
}
#define CP_COMMIT() asm volatile("cp.async.commit_group;")

__device__ __forceinline__ void ldsm4(uint32_t& r0, uint32_t& r1, uint32_t& r2,
                                      uint32_t& r3, uint32_t addr) {
    asm volatile("ldmatrix.sync.aligned.m8n8.x4.shared.b16 {%0,%1,%2,%3}, [%4];"
                 : "=r"(r0), "=r"(r1), "=r"(r2), "=r"(r3) : "r"(addr));
}
__device__ __forceinline__ void ldsm2(uint32_t& r0, uint32_t& r1, uint32_t addr) {
    asm volatile("ldmatrix.sync.aligned.m8n8.x2.shared.b16 {%0,%1}, [%2];"
                 : "=r"(r0), "=r"(r1) : "r"(addr));
}
__device__ __forceinline__ void mma16816(float* c, const uint32_t* a, const uint32_t* b) {
    asm volatile("mma.sync.aligned.m16n8k16.row.col.f32.bf16.bf16.f32 "
                 "{%0,%1,%2,%3}, {%4,%5,%6,%7}, {%8,%9}, {%0,%1,%2,%3};"
                 : "+f"(c[0]), "+f"(c[1]), "+f"(c[2]), "+f"(c[3])
                 : "r"(a[0]), "r"(a[1]), "r"(a[2]), "r"(a[3]), "r"(b[0]), "r"(b[1]));
}

// ---------------- BN stats (per-block partials) -----------------------------
__global__ void stats_kernel(const float* __restrict__ x, int rowsPerBlock, int nrows) {
    int c = threadIdx.x;
    int b = blockIdx.x;
    long r0 = (long)b * rowsPerBlock;
    float s = 0.f, s2 = 0.f;
    for (int r = 0; r < rowsPerBlock; ++r) {
        long row = r0 + r;
        if (row < nrows) {
            float v = x[row * 768 + c];
            s += v; s2 += v * v;
        }
    }
    g_psum[b * 768 + c] = s;
    g_psumsq[b * 768 + c] = s2;
}

__global__ void prep_kernel(const float* __restrict__ gamma,
                            const float* __restrict__ beta, int nrows, int nblk) {
    int c = threadIdx.x;
    double s = 0.0, s2 = 0.0;
    for (int b = 0; b < nblk; ++b) {
        s  += (double)g_psum[b * 768 + c];
        s2 += (double)g_psumsq[b * 768 + c];
    }
    double mean = s / (double)nrows;
    double var  = s2 / (double)nrows - mean * mean;
    float sc = gamma[c] * (float)(1.0 / sqrt(var + 1e-5));
    g_scale[c] = sc;
    g_shift[c] = beta[c] - (float)mean * sc;
}

// ------------- merged L0 prep: split_x + repackW0 + gconst0 ------------------
__global__ void prep_all_l0(const float4* __restrict__ x4,
                            const float* __restrict__ w,
                            const float* __restrict__ bih,
                            const float* __restrict__ bhh,
                            int nsplit) {
    int bid = blockIdx.x;
    int tid = threadIdx.x;
    if (bid < nsplit) {
        size_t i = (size_t)bid * 256 + tid;
        float4 v = x4[i];
        int c = (int)(i % 192) * 4;
        v.x *= g_scale[c + 0]; v.y *= g_scale[c + 1];
        v.z *= g_scale[c + 2]; v.w *= g_scale[c + 3];
        __nv_bfloat16 h0 = __float2bfloat16(v.x);
        __nv_bfloat16 h1 = __float2bfloat16(v.y);
        __nv_bfloat16 h2 = __float2bfloat16(v.z);
        __nv_bfloat16 h3 = __float2bfloat16(v.w);
        __nv_bfloat16 l0 = __float2bfloat16(v.x - __bfloat162float(h0));
        __nv_bfloat16 l1 = __float2bfloat16(v.y - __bfloat162float(h1));
        __nv_bfloat16 l2 = __float2bfloat16(v.z - __bfloat162float(h2));
        __nv_bfloat16 l3 = __float2bfloat16(v.w - __bfloat162float(h3));
        __nv_bfloat162* ph = (__nv_bfloat162*)g_xh;
        __nv_bfloat162* pl = (__nv_bfloat162*)g_xl;
        ph[i * 2 + 0] = __halves2bfloat162(h0, h1);
        ph[i * 2 + 1] = __halves2bfloat162(h2, h3);
        pl[i * 2 + 0] = __halves2bfloat162(l0, l1);
        pl[i * 2 + 1] = __halves2bfloat162(l2, l3);
    } else if (bid < nsplit + 4608) {
        int idx = (bid - nsplit) * 256 + tid;      // < 1536*768
        int d = idx % 768;
        int n = idx / 768;
        int g = n % 3, j = n / 3;
        int dir = j >> 8, jj = j & 255;
        int grow = (g == 0) ? jj : (g == 1 ? 512 + jj : 768 + jj);
        float v = w[(size_t)(dir * 1024 + grow) * 768 + d];
        __nv_bfloat16 h = __float2bfloat16(v);
        g_W0h[idx] = h;
        g_W0l[idx] = __float2bfloat16(v - __bfloat162float(h));
    } else {
        int warpId = (bid - nsplit - 4608) * 8 + (tid >> 5);   // < 1536
        int lane = tid & 31;
        int g = warpId % 3, j = warpId / 3;
        int dir = j >> 8, jj = j & 255;
        int grow = (g == 0) ? jj : (g == 1 ? 512 + jj : 768 + jj);
        const float* wr = w + (size_t)(dir * 1024 + grow) * 768;
        float s = 0.f;
        for (int k = lane; k < 768; k += 32) s += g_shift[k] * wr[k];
        #pragma unroll
        for (int o = 16; o; o >>= 1) s += __shfl_down_sync(0xffffffffu, s, o);
        if (!lane) g_gc0[warpId] = s + bih[dir * 1024 + grow] + bhh[dir * 1024 + grow];
    }
}

// ------------- merged L1 prep: repackW1 + gconst1 ----------------------------
__global__ void prep_l1(const float* __restrict__ w,
                        const float* __restrict__ bih,
                        const float* __restrict__ bhh) {
    int bid = blockIdx.x;
    int tid = threadIdx.x;
    if (bid < 3072) {
        int idx = bid * 256 + tid;                 // < 1536*512
        int d = idx % 512;
        int n = idx / 512;
        int g = n % 3, j = n / 3;
        int dir = j >> 8, jj = j & 255;
        int grow = (g == 0) ? jj : (g == 1 ? 512 + jj : 768 + jj);
        float v = w[(size_t)(dir * 1024 + grow) * 512 + d];
        __nv_bfloat16 h = __float2bfloat16(v);
        g_W1h[idx] = h;
        g_W1l[idx] = __float2bfloat16(v - __bfloat162float(h));
    } else {
        int n = (bid - 3072) * 256 + tid;
        if (n >= 1536) return;
        int g = n % 3, j = n / 3;
        int dir = j >> 8, jj = j & 255;
        int grow = (g == 0) ? jj : (g == 1 ? 512 + jj : 768 + jj);
        g_gc1[n] = bih[dir * 1024 + grow] + bhh[dir * 1024 + grow];
    }
}

// ---------------- HMMA GEMM + fused LSTM epilogue ---------------------------
// CTA 128 rows x 96 gate cols (= 32 h-units x3), 8 warps (2M x 4N), warp 64x24.
// bf16x3: acc += Ah*Bh + Ah*Bl + Al*Bh. 3-stage pipeline, ONE barrier/chunk.
#define GBUF   35840
#define OFF_AL 10240
#define OFF_BH 20480
#define OFF_BL 28160
#define SMEM_TC (3 * GBUF)

template <bool L0>
__global__ void __launch_bounds__(256) gemm_lstm_tc() {
    constexpr int K = L0 ? 768 : 512;
    constexpr int NCH = K / 32;
    const __nv_bfloat16* __restrict__ Ah = L0 ? g_xh : g_h1h;
    const __nv_bfloat16* __restrict__ Al = L0 ? g_xl : g_h1l;
    const __nv_bfloat16* __restrict__ Bh = L0 ? g_W0h : g_W1h;
    const __nv_bfloat16* __restrict__ Bl = L0 ? g_W0l : g_W1l;
    const float* __restrict__ gc = L0 ? g_gc0 : g_gc1;

    extern __shared__ char smem[];
    uint32_t sbase = (uint32_t)__cvta_generic_to_shared(smem);

    const int tid = threadIdx.x;
    const int m0 = blockIdx.y * 128;
    const int n0 = blockIdx.x * 96;

    auto issue = [&](int kt, int b) {
        uint32_t sA = sbase + b * GBUF;
        #pragma unroll
        for (int it = 0; it < 2; ++it) {
            int idx = tid + it * 256;
            int r = idx >> 2, q = idx & 3;
            uint32_t d = sA + r * 80 + q * 16;
            const size_t go = (size_t)(m0 + r) * K + kt + q * 8;
            cpasync16(d, Ah + go);
            cpasync16(d + OFF_AL, Al + go);
        }
        {
            int r = tid >> 2, q = tid & 3;
            uint32_t d = sA + OFF_BH + r * 80 + q * 16;
            const size_t go = (size_t)(n0 + r) * K + kt + q * 8;
            cpasync16(d, Bh + go);
            cpasync16(d + (OFF_BL - OFF_BH), Bl + go);
            if (tid < 128) {
                int r2 = 64 + (tid >> 2), q2 = tid & 3;
                uint32_t d2 = sA + OFF_BH + r2 * 80 + q2 * 16;
                const size_t go2 = (size_t)(n0 + r2) * K + kt + q2 * 8;
                cpasync16(d2, Bh + go2);
                cpasync16(d2 + (OFF_BL - OFF_BH), Bl + go2);
            }
        }
        CP_COMMIT();
    };

    const int lane = tid & 31, wid = tid >> 5;
    const int wm = (wid & 1) * 64;
    const int wn = (wid >> 1) * 24;

    const int msel   = lane >> 3;
    const int arow_f = (msel & 1) * 8 + (lane & 7);
    const int akoff  = (msel >> 1) * 8;
    const int brow_f = (msel >> 1) * 8 + (lane & 7);
    const int bkoff  = (msel & 1) * 8;
    const int l2     = lane & 15;
    const int b2row  = 16 + (l2 & 7);
    const int b2koff = ((l2 >> 3) & 1) * 8;

    float acc[4][3][4];
    #pragma unroll
    for (int mt = 0; mt < 4; mt++)
        #pragma unroll
        for (int nb = 0; nb < 3; nb++)
            #pragma unroll
            for (int r = 0; r < 4; r++) acc[mt][nb][r] = 0.f;

    issue(0, 0);
    issue(32, 1);

    #pragma unroll 1
    for (int c = 0; c < NCH; ++c) {
        asm volatile("cp.async.wait_group 1;" ::: "memory");
        __syncthreads();
        // buffer (c+2)%3 == (c-1)%3: its compute finished before the barrier
        if (c + 2 < NCH) issue((c + 2) * 32, (c + 2) % 3);
        else             CP_COMMIT();          // keep wait count uniform
        uint32_t sA = sbase + (c % 3) * GBUF;

        #pragma unroll
        for (int ks = 0; ks < 32; ks += 16) {
            uint32_t ah[4][4], al[4][4], bh[3][2], bl[3][2];
            {
                uint32_t bd = sA + OFF_BH + (wn + brow_f) * 80 + (ks + bkoff) * 2;
                ldsm4(bh[0][0], bh[0][1], bh[1][0], bh[1][1], bd);
                ldsm4(bl[0][0], bl[0][1], bl[1][0], bl[1][1], bd + (OFF_BL - OFF_BH));
                uint32_t bd2 = sA + OFF_BH + (wn + b2row) * 80 + (ks + b2koff) * 2;
                ldsm2(bh[2][0], bh[2][1], bd2);
                ldsm2(bl[2][0], bl[2][1], bd2 + (OFF_BL - OFF_BH));
            }
            #pragma unroll
            for (int mt = 0; mt < 4; mt++) {
                uint32_t ad = sA + (wm + mt * 16 + arow_f) * 80 + (ks + akoff) * 2;
                ldsm4(ah[mt][0], ah[mt][1], ah[mt][2], ah[mt][3], ad);
                ldsm4(al[mt][0], al[mt][1], al[mt][2], al[mt][3], ad + OFF_AL);
            }
            #pragma unroll
            for (int mt = 0; mt < 4; mt++)
                #pragma unroll
                for (int nb = 0; nb < 3; nb++) {
                    mma16816(acc[mt][nb], ah[mt], bh[nb]);
                    mma16816(acc[mt][nb], ah[mt], bl[nb]);
                    mma16816(acc[mt][nb], al[mt], bh[nb]);
                }
        }
    }
    __syncthreads();

    float* sC = (float*)smem;
    #pragma unroll
    for (int mt = 0; mt < 4; mt++)
        #pragma unroll
        for (int nb = 0; nb < 3; nb++) {
            int r = wm + mt * 16 + (lane >> 2);
            int cc = wn + nb * 8 + (lane & 3) * 2;
            sC[r * 100 + cc]           = acc[mt][nb][0];
            sC[r * 100 + cc + 1]       = acc[mt][nb][1];
            sC[(r + 8) * 100 + cc]     = acc[mt][nb][2];
            sC[(r + 8) * 100 + cc + 1] = acc[mt][nb][3];
        }
    __syncthreads();

    #pragma unroll
    for (int t = 0; t < 16; t++) {
        int idx = t * 256 + tid;
        int r = idx >> 5, j = idx & 31;
        float iv = sC[r * 100 + 3 * j + 0] + gc[n0 + 3 * j + 0];
        float gv = sC[r * 100 + 3 * j + 1] + gc[n0 + 3 * j + 1];
        float ov = sC[r * 100 + 3 * j + 2] + gc[n0 + 3 * j + 2];
        float cv = (1.f / (1.f + expf(-iv))) * tanhf(gv);
        float hv = (1.f / (1.f + expf(-ov))) * tanhf(cv);
        size_t o = (size_t)(m0 + r) * 512 + (size_t)(n0 / 3 + j);
        if (L0) {
            __nv_bfloat16 hh = __float2bfloat16(hv);
            g_h1h[o] = hh;
            g_h1l[o] = __float2bfloat16(hv - __bfloat162float(hh));
        } else {
            g_h2[o] = hv;
        }
    }
}

// ---------------- FC ----------------
__global__ __launch_bounds__(256)
void fc_kernel(const float* __restrict__ fcw, const float* __restrict__ fcb,
               float* __restrict__ e, int nrows) {
    __shared__ float w0[512], w1[512];
    for (int i = threadIdx.x; i < 512; i += blockDim.x) {
        w0[i] = fcw[i];
        w1[i] = fcw[512 + i];
    }
    __syncthreads();
    int warp = (int)((blockIdx.x * (size_t)blockDim.x + threadIdx.x) >> 5);
    int lane = threadIdx.x & 31;
    if (warp >= nrows) return;
    const float* h = g_h2 + (size_t)warp * 512;
    float s0 = 0.f, s1 = 0.f;
    #pragma unroll
    for (int k = lane * 4; k < 512; k += 128) {
        float4 hv = *(const float4*)(h + k);
        s0 += hv.x * w0[k] + hv.y * w0[k + 1] + hv.z * w0[k + 2] + hv.w * w0[k + 3];
        s1 += hv.x * w1[k] + hv.y * w1[k + 1] + hv.z * w1[k + 2] + hv.w * w1[k + 3];
    }
    #pragma unroll
    for (int o = 16; o; o >>= 1) {
        s0 += __shfl_down_sync(0xffffffffu, s0, o);
        s1 += __shfl_down_sync(0xffffffffu, s1, o);
    }
    if (!lane) {
        e[(size_t)warp * 2 + 0] = s0 + fcb[0];
        e[(size_t)warp * 2 + 1] = s1 + fcb[1];
    }
}

// ---------------- CRF NLL: parallel log-semiring reduce ----------------------
__device__ __forceinline__ double lse2(double a, double b) {
    double m = fmax(a, b), n = fmin(a, b);
    return m + log1p(exp(n - m));
}

__global__ __launch_bounds__(256)
void crf_part(const float* __restrict__ e, const int* __restrict__ tags,
              const float* __restrict__ trans, int N) {
    __shared__ double sP[256][4];
    __shared__ double sN[256];
    const int t = threadIdx.x;
    const long n = (long)blockIdx.x * 256 + t;
    const double T00 = trans[0], T01 = trans[1], T10 = trans[2], T11 = trans[3];
    const double NEG = -1e30;

    double m00 = 0.0, m01 = NEG, m10 = NEG, m11 = 0.0;
    double np = 0.0;
    if (n < N) {
        int tg = tags[n];
        np = (double)e[n * 2 + tg];
        if (n >= 1) {
            int tp = tags[n - 1];
            np += (tp == 0) ? (tg == 0 ? T00 : T01) : (tg == 0 ? T10 : T11);
            double e0 = (double)e[n * 2 + 0];
            double e1 = (double)e[n * 2 + 1];
            m00 = T00 + e0; m01 = T01 + e1;
            m10 = T10 + e0; m11 = T11 + e1;
        }
    }
    sP[t][0] = m00; sP[t][1] = m01; sP[t][2] = m10; sP[t][3] = m11;
    sN[t] = np;
    __syncthreads();

    for (int half = 128; half >= 1; half >>= 1) {
        double a0, a1, a2, a3, b0, b1, b2, b3, nn;
        bool act = t < half;
        if (act) {
            a0 = sP[2 * t][0];     a1 = sP[2 * t][1];
            a2 = sP[2 * t][2];     a3 = sP[2 * t][3];
            b0 = sP[2 * t + 1][0]; b1 = sP[2 * t + 1][1];
            b2 = sP[2 * t + 1][2]; b3 = sP[2 * t + 1][3];
            nn = sN[2 * t] + sN[2 * t + 1];
        }
        __syncthreads();
        if (act) {
            sP[t][0] = lse2(a0 + b0, a1 + b2);
            sP[t][1] = lse2(a0 + b1, a1 + b3);
            sP[t][2] = lse2(a2 + b0, a3 + b2);
            sP[t][3] = lse2(a2 + b1, a3 + b3);
            sN[t] = nn;
        }
        __syncthreads();
    }
    if (t == 0) {
        g_crfP[blockIdx.x][0] = sP[0][0];
        g_crfP[blockIdx.x][1] = sP[0][1];
        g_crfP[blockIdx.x][2] = sP[0][2];
        g_crfP[blockIdx.x][3] = sP[0][3];
        g_crfN[blockIdx.x] = sN[0];
    }
}

__global__ __launch_bounds__(256)
void crf_comb(const float* __restrict__ e, const int* __restrict__ tags,
              const float* __restrict__ startv, const float* __restrict__ endv,
              float* __restrict__ loss_out, int N, int nb) {
    __shared__ double sP[256][4];
    __shared__ double sN[256];
    const int t = threadIdx.x;
    const double NEG = -1e30;
    if (t < nb) {
        sP[t][0] = g_crfP[t][0]; sP[t][1] = g_crfP[t][1];
        sP[t][2] = g_crfP[t][2]; sP[t][3] = g_crfP[t][3];
        sN[t] = g_crfN[t];
    } else {
        sP[t][0] = 0.0; sP[t][1] = NEG; sP[t][2] = NEG; sP[t][3] = 0.0;
        sN[t] = 0.0;
    }
    __syncthreads();

    for (int half = 128; half >= 1; half >>= 1) {
        double a0, a1, a2, a3, b0, b1, b2, b3, nn;
        bool act = t < half;
        if (act) {
            a0 = sP[2 * t][0];     a1 = sP[2 * t][1];
            a2 = sP[2 * t][2];     a3 = sP[2 * t][3];
            b0 = sP[2 * t + 1][0]; b1 = sP[2 * t + 1][1];
            b2 = sP[2 * t + 1][2]; b3 = sP[2 * t + 1][3];
            nn = sN[2 * t] + sN[2 * t + 1];
        }
        __syncthreads();
        if (act) {
            sP[t][0] = lse2(a0 + b0, a1 + b2);
            sP[t][1] = lse2(a0 + b1, a1 + b3);
            sP[t][2] = lse2(a2 + b0, a3 + b2);
            sP[t][3] = lse2(a2 + b1, a3 + b3);
            sN[t] = nn;
        }
        __syncthreads();
    }

    if (t == 0) {
        double num = sN[0] + (double)startv[tags[0]] + (double)endv[tags[N - 1]];
        double a0 = (double)startv[0] + (double)e[0];
        double a1 = (double)startv[1] + (double)e[1];
        double f0 = lse2(a0 + sP[0][0], a1 + sP[0][2]);
        double f1 = lse2(a0 + sP[0][1], a1 + sP[0][3]);
        double den = lse2(f0 + (double)endv[0], f1 + (double)endv[1]);
        loss_out[0] = (float)(den - num);
    }
}

// ---------------- launch ----------------
extern "C" void kernel_launch(void* const* d_in, const int* in_sizes, int n_in,
                              void* d_out, int out_size) {
    const float* x        = (const float*)d_in[0];
    const float* gamma    = (const float*)d_in[1];
    const float* beta     = (const float*)d_in[2];
    const float* w_ih_l0  = (const float*)d_in[3];
    const float* b_ih_l0  = (const float*)d_in[5];
    const float* b_hh_l0  = (const float*)d_in[6];
    const float* w_ih_l1  = (const float*)d_in[7];
    const float* b_ih_l1  = (const float*)d_in[9];
    const float* b_hh_l1  = (const float*)d_in[10];
    const float* fc_w     = (const float*)d_in[11];
    const float* fc_b     = (const float*)d_in[12];
    const float* crf_start= (const float*)d_in[13];
    const float* crf_end  = (const float*)d_in[14];
    const float* crf_trans= (const float*)d_in[15];
    const int*   labels   = (const int*)d_in[16];

    int N = in_sizes[0] / 768;      // 65536
    float* out = (float*)d_out;
    float* e = out + 1;

    cudaFuncSetAttribute((const void*)gemm_lstm_tc<true>,
                         cudaFuncAttributeMaxDynamicSharedMemorySize, SMEM_TC);
    cudaFuncSetAttribute((const void*)gemm_lstm_tc<false>,
                         cudaFuncAttributeMaxDynamicSharedMemorySize, SMEM_TC);

    int rpb = (N + 127) / 128;
    int nblk = (N + rpb - 1) / rpb;
    int nsplit = N * 768 / 4 / 256;                        // 49152

    stats_kernel<<<nblk, 768>>>(x, rpb, N);                                    // 0
    prep_kernel<<<1, 768>>>(gamma, beta, N, nblk);                             // 1
    prep_all_l0<<<nsplit + 4608 + 192, 256>>>((const float4*)x, w_ih_l0,
                                              b_ih_l0, b_hh_l0, nsplit);       // 2
    dim3 gg(16, N / 128);
    gemm_lstm_tc<true ><<<gg, 256, SMEM_TC>>>();                               // 3  <- ncu
    prep_l1<<<3078, 256>>>(w_ih_l1, b_ih_l1, b_hh_l1);                         // 4
    gemm_lstm_tc<false><<<gg, 256, SMEM_TC>>>();                               // 5
    fc_kernel<<<(N / 8), 256>>>(fc_w, fc_b, e, N);                             // 6
    crf_part<<<(N + 255) / 256, 256>>>(e, labels, crf_trans, N);               // 7
    crf_comb<<<1, 256>>>(e, labels, crf_start, crf_end, out, N, (N + 255) / 256); // 8
}

// round 9
// speedup vs baseline: 3.0781x; 1.2023x over previous
#include <cuda_runtime.h>
#include <cuda_fp16.h>
#include <math.h>
#include <stdint.h>

#define NROWS 65536

// ---------------- scratch (device globals; no allocation allowed) ----------
__device__ float  g_psum[128 * 768];
__device__ float  g_psumsq[128 * 768];
__device__ float  g_scale[768];
__device__ float  g_shift[768];
__device__ __half g_xh[(size_t)NROWS * 768];
__device__ __half g_xl[(size_t)NROWS * 768];
__device__ __half g_W0[1536 * 768];
__device__ __half g_W1[1536 * 512];
__device__ __half g_h1h[(size_t)NROWS * 512];
__device__ __half g_h1l[(size_t)NROWS * 512];
__device__ float g_h2[(size_t)NROWS * 512];
__device__ float g_gc0[1536];
__device__ float g_gc1[1536];
__device__ double g_crfP[256][4];
__device__ double g_crfN[256];

// ---------------- helpers ----------------
__device__ __forceinline__ void cpasync16(uint32_t dst, const void* src) {
    asm volatile("cp.async.cg.shared.global [%0], [%1], 16;" :: "r"(dst), "l"(src));
}
#define CP_COMMIT() asm volatile("cp.async.commit_group;")

__device__ __forceinline__ void ldsm4(uint32_t& r0, uint32_t& r1, uint32_t& r2,
                                      uint32_t& r3, uint32_t addr) {
    asm volatile("ldmatrix.sync.aligned.m8n8.x4.shared.b16 {%0,%1,%2,%3}, [%4];"
                 : "=r"(r0), "=r"(r1), "=r"(r2), "=r"(r3) : "r"(addr));
}
__device__ __forceinline__ void ldsm2(uint32_t& r0, uint32_t& r1, uint32_t addr) {
    asm volatile("ldmatrix.sync.aligned.m8n8.x2.shared.b16 {%0,%1}, [%2];"
                 : "=r"(r0), "=r"(r1) : "r"(addr));
}
__device__ __forceinline__ void mma16816h(float* c, const uint32_t* a, const uint32_t* b) {
    asm volatile("mma.sync.aligned.m16n8k16.row.col.f32.f16.f16.f32 "
                 "{%0,%1,%2,%3}, {%4,%5,%6,%7}, {%8,%9}, {%0,%1,%2,%3};"
                 : "+f"(c[0]), "+f"(c[1]), "+f"(c[2]), "+f"(c[3])
                 : "r"(a[0]), "r"(a[1]), "r"(a[2]), "r"(a[3]), "r"(b[0]), "r"(b[1]));
}

// ---------------- BN stats (per-block partials) -----------------------------
__global__ void stats_kernel(const float* __restrict__ x, int rowsPerBlock, int nrows) {
    int c = threadIdx.x;
    int b = blockIdx.x;
    long r0 = (long)b * rowsPerBlock;
    float s = 0.f, s2 = 0.f;
    for (int r = 0; r < rowsPerBlock; ++r) {
        long row = r0 + r;
        if (row < nrows) {
            float v = x[row * 768 + c];
            s += v; s2 += v * v;
        }
    }
    g_psum[b * 768 + c] = s;
    g_psumsq[b * 768 + c] = s2;
}

__global__ void prep_kernel(const float* __restrict__ gamma,
                            const float* __restrict__ beta, int nrows, int nblk) {
    int c = threadIdx.x;
    double s = 0.0, s2 = 0.0;
    for (int b = 0; b < nblk; ++b) {
        s  += (double)g_psum[b * 768 + c];
        s2 += (double)g_psumsq[b * 768 + c];
    }
    double mean = s / (double)nrows;
    double var  = s2 / (double)nrows - mean * mean;
    float sc = gamma[c] * (float)(1.0 / sqrt(var + 1e-5));
    g_scale[c] = sc;
    g_shift[c] = beta[c] - (float)mean * sc;
}

// ------------- merged L0 prep: split_x(fp16 hi/lo) + repackW0(fp16) + gconst0
__global__ void prep_all_l0(const float4* __restrict__ x4,
                            const float* __restrict__ w,
                            const float* __restrict__ bih,
                            const float* __restrict__ bhh,
                            int nsplit) {
    int bid = blockIdx.x;
    int tid = threadIdx.x;
    if (bid < nsplit) {
        size_t i = (size_t)bid * 256 + tid;
        float4 v = x4[i];
        int c = (int)(i % 192) * 4;
        v.x *= g_scale[c + 0]; v.y *= g_scale[c + 1];
        v.z *= g_scale[c + 2]; v.w *= g_scale[c + 3];
        __half h0 = __float2half(v.x);
        __half h1 = __float2half(v.y);
        __half h2 = __float2half(v.z);
        __half h3 = __float2half(v.w);
        __half l0 = __float2half(v.x - __half2float(h0));
        __half l1 = __float2half(v.y - __half2float(h1));
        __half l2 = __float2half(v.z - __half2float(h2));
        __half l3 = __float2half(v.w - __half2float(h3));
        __half2* ph = (__half2*)g_xh;
        __half2* pl = (__half2*)g_xl;
        ph[i * 2 + 0] = __halves2half2(h0, h1);
        ph[i * 2 + 1] = __halves2half2(h2, h3);
        pl[i * 2 + 0] = __halves2half2(l0, l1);
        pl[i * 2 + 1] = __halves2half2(l2, l3);
    } else if (bid < nsplit + 4608) {
        int idx = (bid - nsplit) * 256 + tid;      // < 1536*768
        int d = idx % 768;
        int n = idx / 768;
        int g = n % 3, j = n / 3;
        int dir = j >> 8, jj = j & 255;
        int grow = (g == 0) ? jj : (g == 1 ? 512 + jj : 768 + jj);
        float v = w[(size_t)(dir * 1024 + grow) * 768 + d];
        g_W0[idx] = __float2half(v);
    } else {
        int warpId = (bid - nsplit - 4608) * 8 + (tid >> 5);   // < 1536
        int lane = tid & 31;
        int g = warpId % 3, j = warpId / 3;
        int dir = j >> 8, jj = j & 255;
        int grow = (g == 0) ? jj : (g == 1 ? 512 + jj : 768 + jj);
        const float* wr = w + (size_t)(dir * 1024 + grow) * 768;
        float s = 0.f;
        for (int k = lane; k < 768; k += 32) s += g_shift[k] * wr[k];
        #pragma unroll
        for (int o = 16; o; o >>= 1) s += __shfl_down_sync(0xffffffffu, s, o);
        if (!lane) g_gc0[warpId] = s + bih[dir * 1024 + grow] + bhh[dir * 1024 + grow];
    }
}

// ------------- merged L1 prep: repackW1(fp16) + gconst1 ----------------------
__global__ void prep_l1(const float* __restrict__ w,
                        const float* __restrict__ bih,
                        const float* __restrict__ bhh) {
    int bid = blockIdx.x;
    int tid = threadIdx.x;
    if (bid < 3072) {
        int idx = bid * 256 + tid;                 // < 1536*512
        int d = idx % 512;
        int n = idx / 512;
        int g = n % 3, j = n / 3;
        int dir = j >> 8, jj = j & 255;
        int grow = (g == 0) ? jj : (g == 1 ? 512 + jj : 768 + jj);
        float v = w[(size_t)(dir * 1024 + grow) * 512 + d];
        g_W1[idx] = __float2half(v);
    } else {
        int n = (bid - 3072) * 256 + tid;
        if (n >= 1536) return;
        int g = n % 3, j = n / 3;
        int dir = j >> 8, jj = j & 255;
        int grow = (g == 0) ? jj : (g == 1 ? 512 + jj : 768 + jj);
        g_gc1[n] = bih[dir * 1024 + grow] + bhh[dir * 1024 + grow];
    }
}

// ---------------- HMMA GEMM + fused LSTM epilogue ---------------------------
// CTA 128 rows x 96 gate cols, 8 warps (2M x 4N), warp 64x24.
// fp16x2: acc += Xh*W + Xl*W (W single fp16). 3-stage pipeline, 1 barrier/chunk.
// Stage: Xh 128x80B=10240, Xl +10240, W +20480 (96x80B=7680). STAGE=28160.
#define GBUF   28160
#define OFF_AL 10240
#define OFF_B  20480
#define SMEM_TC (3 * GBUF)

template <bool L0>
__global__ void __launch_bounds__(256) gemm_lstm_tc() {
    constexpr int K = L0 ? 768 : 512;
    constexpr int NCH = K / 32;
    const __half* __restrict__ Ah = L0 ? g_xh : g_h1h;
    const __half* __restrict__ Al = L0 ? g_xl : g_h1l;
    const __half* __restrict__ Bw = L0 ? g_W0 : g_W1;
    const float* __restrict__ gc = L0 ? g_gc0 : g_gc1;

    extern __shared__ char smem[];
    uint32_t sbase = (uint32_t)__cvta_generic_to_shared(smem);

    const int tid = threadIdx.x;
    const int m0 = blockIdx.y * 128;
    const int n0 = blockIdx.x * 96;

    auto issue = [&](int kt, int b) {
        uint32_t sA = sbase + b * GBUF;
        #pragma unroll
        for (int it = 0; it < 2; ++it) {
            int idx = tid + it * 256;
            int r = idx >> 2, q = idx & 3;
            uint32_t d = sA + r * 80 + q * 16;
            const size_t go = (size_t)(m0 + r) * K + kt + q * 8;
            cpasync16(d, Ah + go);
            cpasync16(d + OFF_AL, Al + go);
        }
        {
            int r = tid >> 2, q = tid & 3;
            uint32_t d = sA + OFF_B + r * 80 + q * 16;
            const size_t go = (size_t)(n0 + r) * K + kt + q * 8;
            cpasync16(d, Bw + go);
            if (tid < 128) {
                int r2 = 64 + (tid >> 2), q2 = tid & 3;
                uint32_t d2 = sA + OFF_B + r2 * 80 + q2 * 16;
                const size_t go2 = (size_t)(n0 + r2) * K + kt + q2 * 8;
                cpasync16(d2, Bw + go2);
            }
        }
        CP_COMMIT();
    };

    const int lane = tid & 31, wid = tid >> 5;
    const int wm = (wid & 1) * 64;
    const int wn = (wid >> 1) * 24;

    const int msel   = lane >> 3;
    const int arow_f = (msel & 1) * 8 + (lane & 7);
    const int akoff  = (msel >> 1) * 8;
    const int brow_f = (msel >> 1) * 8 + (lane & 7);
    const int bkoff  = (msel & 1) * 8;
    const int l2     = lane & 15;
    const int b2row  = 16 + (l2 & 7);
    const int b2koff = ((l2 >> 3) & 1) * 8;

    float acc[4][3][4];
    #pragma unroll
    for (int mt = 0; mt < 4; mt++)
        #pragma unroll
        for (int nb = 0; nb < 3; nb++)
            #pragma unroll
            for (int r = 0; r < 4; r++) acc[mt][nb][r] = 0.f;

    issue(0, 0);
    issue(32, 1);

    #pragma unroll 1
    for (int c = 0; c < NCH; ++c) {
        asm volatile("cp.async.wait_group 1;" ::: "memory");
        __syncthreads();
        // buffer (c+2)%3 == (c-1)%3: its compute finished before the barrier
        if (c + 2 < NCH) issue((c + 2) * 32, (c + 2) % 3);
        else             CP_COMMIT();          // keep wait count uniform
        uint32_t sA = sbase + (c % 3) * GBUF;

        #pragma unroll
        for (int ks = 0; ks < 32; ks += 16) {
            uint32_t ah[4][4], al[4][4], bw[3][2];
            {
                uint32_t bd = sA + OFF_B + (wn + brow_f) * 80 + (ks + bkoff) * 2;
                ldsm4(bw[0][0], bw[0][1], bw[1][0], bw[1][1], bd);
                uint32_t bd2 = sA + OFF_B + (wn + b2row) * 80 + (ks + b2koff) * 2;
                ldsm2(bw[2][0], bw[2][1], bd2);
            }
            #pragma unroll
            for (int mt = 0; mt < 4; mt++) {
                uint32_t ad = sA + (wm + mt * 16 + arow_f) * 80 + (ks + akoff) * 2;
                ldsm4(ah[mt][0], ah[mt][1], ah[mt][2], ah[mt][3], ad);
                ldsm4(al[mt][0], al[mt][1], al[mt][2], al[mt][3], ad + OFF_AL);
            }
            #pragma unroll
            for (int mt = 0; mt < 4; mt++)
                #pragma unroll
                for (int nb = 0; nb < 3; nb++) {
                    mma16816h(acc[mt][nb], ah[mt], bw[nb]);
                    mma16816h(acc[mt][nb], al[mt], bw[nb]);
                }
        }
    }
    __syncthreads();

    float* sC = (float*)smem;
    #pragma unroll
    for (int mt = 0; mt < 4; mt++)
        #pragma unroll
        for (int nb = 0; nb < 3; nb++) {
            int r = wm + mt * 16 + (lane >> 2);
            int cc = wn + nb * 8 + (lane & 3) * 2;
            sC[r * 100 + cc]           = acc[mt][nb][0];
            sC[r * 100 + cc + 1]       = acc[mt][nb][1];
            sC[(r + 8) * 100 + cc]     = acc[mt][nb][2];
            sC[(r + 8) * 100 + cc + 1] = acc[mt][nb][3];
        }
    __syncthreads();

    #pragma unroll
    for (int t = 0; t < 16; t++) {
        int idx = t * 256 + tid;
        int r = idx >> 5, j = idx & 31;
        float iv = sC[r * 100 + 3 * j + 0] + gc[n0 + 3 * j + 0];
        float gv = sC[r * 100 + 3 * j + 1] + gc[n0 + 3 * j + 1];
        float ov = sC[r * 100 + 3 * j + 2] + gc[n0 + 3 * j + 2];
        float cv = (1.f / (1.f + expf(-iv))) * tanhf(gv);
        float hv = (1.f / (1.f + expf(-ov))) * tanhf(cv);
        size_t o = (size_t)(m0 + r) * 512 + (size_t)(n0 / 3 + j);
        if (L0) {
            __half hh = __float2half(hv);
            g_h1h[o] = hh;
            g_h1l[o] = __float2half(hv - __half2float(hh));
        } else {
            g_h2[o] = hv;
        }
    }
}

// ---------------- FC ----------------
__global__ __launch_bounds__(256)
void fc_kernel(const float* __restrict__ fcw, const float* __restrict__ fcb,
               float* __restrict__ e, int nrows) {
    __shared__ float w0[512], w1[512];
    for (int i = threadIdx.x; i < 512; i += blockDim.x) {
        w0[i] = fcw[i];
        w1[i] = fcw[512 + i];
    }
    __syncthreads();
    int warp = (int)((blockIdx.x * (size_t)blockDim.x + threadIdx.x) >> 5);
    int lane = threadIdx.x & 31;
    if (warp >= nrows) return;
    const float* h = g_h2 + (size_t)warp * 512;
    float s0 = 0.f, s1 = 0.f;
    #pragma unroll
    for (int k = lane * 4; k < 512; k += 128) {
        float4 hv = *(const float4*)(h + k);
        s0 += hv.x * w0[k] + hv.y * w0[k + 1] + hv.z * w0[k + 2] + hv.w * w0[k + 3];
        s1 += hv.x * w1[k] + hv.y * w1[k + 1] + hv.z * w1[k + 2] + hv.w * w1[k + 3];
    }
    #pragma unroll
    for (int o = 16; o; o >>= 1) {
        s0 += __shfl_down_sync(0xffffffffu, s0, o);
        s1 += __shfl_down_sync(0xffffffffu, s1, o);
    }
    if (!lane) {
        e[(size_t)warp * 2 + 0] = s0 + fcb[0];
        e[(size_t)warp * 2 + 1] = s1 + fcb[1];
    }
}

// ---------------- CRF NLL: parallel log-semiring reduce ----------------------
__device__ __forceinline__ double lse2(double a, double b) {
    double m = fmax(a, b), n = fmin(a, b);
    return m + log1p(exp(n - m));
}

__global__ __launch_bounds__(256)
void crf_part(const float* __restrict__ e, const int* __restrict__ tags,
              const float* __restrict__ trans, int N) {
    __shared__ double sP[256][4];
    __shared__ double sN[256];
    const int t = threadIdx.x;
    const long n = (long)blockIdx.x * 256 + t;
    const double T00 = trans[0], T01 = trans[1], T10 = trans[2], T11 = trans[3];
    const double NEG = -1e30;

    double m00 = 0.0, m01 = NEG, m10 = NEG, m11 = 0.0;
    double np = 0.0;
    if (n < N) {
        int tg = tags[n];
        np = (double)e[n * 2 + tg];
        if (n >= 1) {
            int tp = tags[n - 1];
            np += (tp == 0) ? (tg == 0 ? T00 : T01) : (tg == 0 ? T10 : T11);
            double e0 = (double)e[n * 2 + 0];
            double e1 = (double)e[n * 2 + 1];
            m00 = T00 + e0; m01 = T01 + e1;
            m10 = T10 + e0; m11 = T11 + e1;
        }
    }
    sP[t][0] = m00; sP[t][1] = m01; sP[t][2] = m10; sP[t][3] = m11;
    sN[t] = np;
    __syncthreads();

    for (int half = 128; half >= 1; half >>= 1) {
        double a0, a1, a2, a3, b0, b1, b2, b3, nn;
        bool act = t < half;
        if (act) {
            a0 = sP[2 * t][0];     a1 = sP[2 * t][1];
            a2 = sP[2 * t][2];     a3 = sP[2 * t][3];
            b0 = sP[2 * t + 1][0]; b1 = sP[2 * t + 1][1];
            b2 = sP[2 * t + 1][2]; b3 = sP[2 * t + 1][3];
            nn = sN[2 * t] + sN[2 * t + 1];
        }
        __syncthreads();
        if (act) {
            sP[t][0] = lse2(a0 + b0, a1 + b2);
            sP[t][1] = lse2(a0 + b1, a1 + b3);
            sP[t][2] = lse2(a2 + b0, a3 + b2);
            sP[t][3] = lse2(a2 + b1, a3 + b3);
            sN[t] = nn;
        }
        __syncthreads();
    }
    if (t == 0) {
        g_crfP[blockIdx.x][0] = sP[0][0];
        g_crfP[blockIdx.x][1] = sP[0][1];
        g_crfP[blockIdx.x][2] = sP[0][2];
        g_crfP[blockIdx.x][3] = sP[0][3];
        g_crfN[blockIdx.x] = sN[0];
    }
}

__global__ __launch_bounds__(256)
void crf_comb(const float* __restrict__ e, const int* __restrict__ tags,
              const float* __restrict__ startv, const float* __restrict__ endv,
              float* __restrict__ loss_out, int N, int nb) {
    __shared__ double sP[256][4];
    __shared__ double sN[256];
    const int t = threadIdx.x;
    const double NEG = -1e30;
    if (t < nb) {
        sP[t][0] = g_crfP[t][0]; sP[t][1] = g_crfP[t][1];
        sP[t][2] = g_crfP[t][2]; sP[t][3] = g_crfP[t][3];
        sN[t] = g_crfN[t];
    } else {
        sP[t][0] = 0.0; sP[t][1] = NEG; sP[t][2] = NEG; sP[t][3] = 0.0;
        sN[t] = 0.0;
    }
    __syncthreads();

    for (int half = 128; half >= 1; half >>= 1) {
        double a0, a1, a2, a3, b0, b1, b2, b3, nn;
        bool act = t < half;
        if (act) {
            a0 = sP[2 * t][0];     a1 = sP[2 * t][1];
            a2 = sP[2 * t][2];     a3 = sP[2 * t][3];
            b0 = sP[2 * t + 1][0]; b1 = sP[2 * t + 1][1];
            b2 = sP[2 * t + 1][2]; b3 = sP[2 * t + 1][3];
            nn = sN[2 * t] + sN[2 * t + 1];
        }
        __syncthreads();
        if (act) {
            sP[t][0] = lse2(a0 + b0, a1 + b2);
            sP[t][1] = lse2(a0 + b1, a1 + b3);
            sP[t][2] = lse2(a2 + b0, a3 + b2);
            sP[t][3] = lse2(a2 + b1, a3 + b3);
            sN[t] = nn;
        }
        __syncthreads();
    }

    if (t == 0) {
        double num = sN[0] + (double)startv[tags[0]] + (double)endv[tags[N - 1]];
        double a0 = (double)startv[0] + (double)e[0];
        double a1 = (double)startv[1] + (double)e[1];
        double f0 = lse2(a0 + sP[0][0], a1 + sP[0][2]);
        double f1 = lse2(a0 + sP[0][1], a1 + sP[0][3]);
        double den = lse2(f0 + (double)endv[0], f1 + (double)endv[1]);
        loss_out[0] = (float)(den - num);
    }
}

// ---------------- launch ----------------
extern "C" void kernel_launch(void* const* d_in, const int* in_sizes, int n_in,
                              void* d_out, int out_size) {
    const float* x        = (const float*)d_in[0];
    const float* gamma    = (const float*)d_in[1];
    const float* beta     = (const float*)d_in[2];
    const float* w_ih_l0  = (const float*)d_in[3];
    const float* b_ih_l0  = (const float*)d_in[5];
    const float* b_hh_l0  = (const float*)d_in[6];
    const float* w_ih_l1  = (const float*)d_in[7];
    const float* b_ih_l1  = (const float*)d_in[9];
    const float* b_hh_l1  = (const float*)d_in[10];
    const float* fc_w     = (const float*)d_in[11];
    const float* fc_b     = (const float*)d_in[12];
    const float* crf_start= (const float*)d_in[13];
    const float* crf_end  = (const float*)d_in[14];
    const float* crf_trans= (const float*)d_in[15];
    const int*   labels   = (const int*)d_in[16];

    int N = in_sizes[0] / 768;      // 65536
    float* out = (float*)d_out;
    float* e = out + 1;

    cudaFuncSetAttribute((const void*)gemm_lstm_tc<true>,
                         cudaFuncAttributeMaxDynamicSharedMemorySize, SMEM_TC);
    cudaFuncSetAttribute((const void*)gemm_lstm_tc<false>,
                         cudaFuncAttributeMaxDynamicSharedMemorySize, SMEM_TC);

    int rpb = (N + 127) / 128;
    int nblk = (N + rpb - 1) / rpb;
    int nsplit = N * 768 / 4 / 256;                        // 49152

    stats_kernel<<<nblk, 768>>>(x, rpb, N);                                    // 0
    prep_kernel<<<1, 768>>>(gamma, beta, N, nblk);                             // 1
    prep_all_l0<<<nsplit + 4608 + 192, 256>>>((const float4*)x, w_ih_l0,
                                              b_ih_l0, b_hh_l0, nsplit);       // 2
    dim3 gg(16, N / 128);
    gemm_lstm_tc<true ><<<gg, 256, SMEM_TC>>>();                               // 3  <- ncu
    prep_l1<<<3078, 256>>>(w_ih_l1, b_ih_l1, b_hh_l1);                         // 4
    gemm_lstm_tc<false><<<gg, 256, SMEM_TC>>>();                               // 5
    fc_kernel<<<(N / 8), 256>>>(fc_w, fc_b, e, N);                             // 6
    crf_part<<<(N + 255) / 256, 256>>>(e, labels, crf_trans, N);               // 7
    crf_comb<<<1, 256>>>(e, labels, crf_start, crf_end, out, N, (N + 255) / 256); // 8
}

// round 12
// speedup vs baseline: 3.7975x; 1.2337x over previous
#include <cuda_runtime.h>
#include <cuda_fp16.h>
#include <math.h>
#include <stdint.h>

#define NROWS 65536

// ---------------- scratch (device globals; no allocation allowed) ----------
__device__ float  g_psum[128 * 768];
__device__ float  g_psumsq[128 * 768];
__device__ float  g_scale[768];
__device__ float  g_shift[768];
__device__ __half g_xh[(size_t)NROWS * 768];
__device__ __half g_xl[(size_t)NROWS * 768];
__device__ __half g_W0[1536 * 768];
__device__ __half g_W1[1536 * 512];
__device__ __half g_h1h[(size_t)NROWS * 512];
__device__ float g_h2[(size_t)NROWS * 512];
__device__ float g_gc0[1536];
__device__ float g_gc1[1536];
__device__ double g_crfP[256][4];
__device__ double g_crfN[256];

// ---------------- helpers ----------------
__device__ __forceinline__ void cpasync16(uint32_t dst, const void* src) {
    asm volatile("cp.async.cg.shared.global [%0], [%1], 16;" :: "r"(dst), "l"(src));
}
#define CP_COMMIT() asm volatile("cp.async.commit_group;")

__device__ __forceinline__ void ldsm4(uint32_t& r0, uint32_t& r1, uint32_t& r2,
                                      uint32_t& r3, uint32_t addr) {
    asm volatile("ldmatrix.sync.aligned.m8n8.x4.shared.b16 {%0,%1,%2,%3}, [%4];"
                 : "=r"(r0), "=r"(r1), "=r"(r2), "=r"(r3) : "r"(addr));
}
__device__ __forceinline__ void ldsm2(uint32_t& r0, uint32_t& r1, uint32_t addr) {
    asm volatile("ldmatrix.sync.aligned.m8n8.x2.shared.b16 {%0,%1}, [%2];"
                 : "=r"(r0), "=r"(r1) : "r"(addr));
}
__device__ __forceinline__ void mma16816h(float* c, const uint32_t* a, const uint32_t* b) {
    asm volatile("mma.sync.aligned.m16n8k16.row.col.f32.f16.f16.f32 "
                 "{%0,%1,%2,%3}, {%4,%5,%6,%7}, {%8,%9}, {%0,%1,%2,%3};"
                 : "+f"(c[0]), "+f"(c[1]), "+f"(c[2]), "+f"(c[3])
                 : "r"(a[0]), "r"(a[1]), "r"(a[2]), "r"(a[3]), "r"(b[0]), "r"(b[1]));
}

// ---------------- BN stats (per-block partials) -----------------------------
__global__ void stats_kernel(const float* __restrict__ x, int rowsPerBlock, int nrows) {
    int c = threadIdx.x;
    int b = blockIdx.x;
    long r0 = (long)b * rowsPerBlock;
    float s = 0.f, s2 = 0.f;
    for (int r = 0; r < rowsPerBlock; ++r) {
        long row = r0 + r;
        if (row < nrows) {
            float v = x[row * 768 + c];
            s += v; s2 += v * v;
        }
    }
    g_psum[b * 768 + c] = s;
    g_psumsq[b * 768 + c] = s2;
}

__global__ void prep_kernel(const float* __restrict__ gamma,
                            const float* __restrict__ beta, int nrows, int nblk) {
    int c = threadIdx.x;
    double s = 0.0, s2 = 0.0;
    for (int b = 0; b < nblk; ++b) {
        s  += (double)g_psum[b * 768 + c];
        s2 += (double)g_psumsq[b * 768 + c];
    }
    double mean = s / (double)nrows;
    double var  = s2 / (double)nrows - mean * mean;
    float sc = gamma[c] * (float)(1.0 / sqrt(var + 1e-5));
    g_scale[c] = sc;
    g_shift[c] = beta[c] - (float)mean * sc;
}

// ------------- merged L0 prep: split_x(fp16 hi/lo) + repackW0(fp16) + gconst0
__global__ void prep_all_l0(const float4* __restrict__ x4,
                            const float* __restrict__ w,
                            const float* __restrict__ bih,
                            const float* __restrict__ bhh,
                            int nsplit) {
    int bid = blockIdx.x;
    int tid = threadIdx.x;
    if (bid < nsplit) {
        size_t i = (size_t)bid * 256 + tid;
        float4 v = x4[i];
        int c = (int)(i % 192) * 4;
        v.x *= g_scale[c + 0]; v.y *= g_scale[c + 1];
        v.z *= g_scale[c + 2]; v.w *= g_scale[c + 3];
        __half h0 = __float2half(v.x);
        __half h1 = __float2half(v.y);
        __half h2 = __float2half(v.z);
        __half h3 = __float2half(v.w);
        __half l0 = __float2half(v.x - __half2float(h0));
        __half l1 = __float2half(v.y - __half2float(h1));
        __half l2 = __float2half(v.z - __half2float(h2));
        __half l3 = __float2half(v.w - __half2float(h3));
        __half2* ph = (__half2*)g_xh;
        __half2* pl = (__half2*)g_xl;
        ph[i * 2 + 0] = __halves2half2(h0, h1);
        ph[i * 2 + 1] = __halves2half2(h2, h3);
        pl[i * 2 + 0] = __halves2half2(l0, l1);
        pl[i * 2 + 1] = __halves2half2(l2, l3);
    } else if (bid < nsplit + 4608) {
        int idx = (bid - nsplit) * 256 + tid;      // < 1536*768
        int d = idx % 768;
        int n = idx / 768;
        int g = n % 3, j = n / 3;
        int dir = j >> 8, jj = j & 255;
        int grow = (g == 0) ? jj : (g == 1 ? 512 + jj : 768 + jj);
        float v = w[(size_t)(dir * 1024 + grow) * 768 + d];
        g_W0[idx] = __float2half(v);
    } else {
        int warpId = (bid - nsplit - 4608) * 8 + (tid >> 5);   // < 1536
        int lane = tid & 31;
        int g = warpId % 3, j = warpId / 3;
        int dir = j >> 8, jj = j & 255;
        int grow = (g == 0) ? jj : (g == 1 ? 512 + jj : 768 + jj);
        const float* wr = w + (size_t)(dir * 1024 + grow) * 768;
        float s = 0.f;
        for (int k = lane; k < 768; k += 32) s += g_shift[k] * wr[k];
        #pragma unroll
        for (int o = 16; o; o >>= 1) s += __shfl_down_sync(0xffffffffu, s, o);
        if (!lane) g_gc0[warpId] = s + bih[dir * 1024 + grow] + bhh[dir * 1024 + grow];
    }
}

// ------------- merged L1 prep: repackW1(fp16) + gconst1 ----------------------
__global__ void prep_l1(const float* __restrict__ w,
                        const float* __restrict__ bih,
                        const float* __restrict__ bhh) {
    int bid = blockIdx.x;
    int tid = threadIdx.x;
    if (bid < 3072) {
        int idx = bid * 256 + tid;                 // < 1536*512
        int d = idx % 512;
        int n = idx / 512;
        int g = n % 3, j = n / 3;
        int dir = j >> 8, jj = j & 255;
        int grow = (g == 0) ? jj : (g == 1 ? 512 + jj : 768 + jj);
        float v = w[(size_t)(dir * 1024 + grow) * 512 + d];
        g_W1[idx] = __float2half(v);
    } else {
        int n = (bid - 3072) * 256 + tid;
        if (n >= 1536) return;
        int g = n % 3, j = n / 3;
        int dir = j >> 8, jj = j & 255;
        int grow = (g == 0) ? jj : (g == 1 ? 512 + jj : 768 + jj);
        g_gc1[n] = bih[dir * 1024 + grow] + bhh[dir * 1024 + grow];
    }
}

// ---------------- HMMA GEMM + fused LSTM epilogue ---------------------------
// CTA 128 rows x 96 gate cols, 8 warps (2M x 4N), warp 64x24.
// L0: fp16x2 (acc += Xh*W + Xl*W). L1: single fp16 product (acc += Xh*W).
// 2-stage pipeline, 3 CTAs/SM via __launch_bounds__(256,3).
#define OFF_AL 10240
#define GBUF0  28160
#define OFF_B0 20480
#define GBUF1  17920
#define OFF_B1 10240
#define SMEM0  (2 * GBUF0)                  // 56320 (>= 51200 epilogue)
#define SMEM1  51200                        // max(2*GBUF1=35840, epilogue 51200)

template <bool L0>
__global__ void __launch_bounds__(256, 3) gemm_lstm_tc() {
    constexpr int K = L0 ? 768 : 512;
    constexpr int NCH = K / 32;
    constexpr int GBUF = L0 ? GBUF0 : GBUF1;
    constexpr int OFF_B = L0 ? OFF_B0 : OFF_B1;
    const __half* __restrict__ Ah = L0 ? g_xh : g_h1h;
    const __half* __restrict__ Bw = L0 ? g_W0 : g_W1;
    const float* __restrict__ gc = L0 ? g_gc0 : g_gc1;

    extern __shared__ char smem[];
    uint32_t sbase = (uint32_t)__cvta_generic_to_shared(smem);

    const int tid = threadIdx.x;
    const int m0 = blockIdx.y * 128;
    const int n0 = blockIdx.x * 96;

    auto issue = [&](int kt, int b) {
        uint32_t sA = sbase + b * GBUF;
        #pragma unroll
        for (int it = 0; it < 2; ++it) {   // A: 128 rows x 4 x16B = 512 transfers
            int idx = tid + it * 256;
            int r = idx >> 2, q = idx & 3;
            uint32_t d = sA + r * 80 + q * 16;
            const size_t go = (size_t)(m0 + r) * K + kt + q * 8;
            cpasync16(d, Ah + go);
            if (L0) cpasync16(d + OFF_AL, g_xl + go);
        }
        {   // B: 96 rows x 4 x16B = 384 transfers on 256 threads
            int r = tid >> 2, q = tid & 3;             // rows 0..63
            uint32_t d = sA + OFF_B + r * 80 + q * 16;
            const size_t go = (size_t)(n0 + r) * K + kt + q * 8;
            cpasync16(d, Bw + go);
            if (tid < 128) {                           // rows 64..95
                int r2 = 64 + (tid >> 2), q2 = tid & 3;
                uint32_t d2 = sA + OFF_B + r2 * 80 + q2 * 16;
                const size_t go2 = (size_t)(n0 + r2) * K + kt + q2 * 8;
                cpasync16(d2, Bw + go2);
            }
        }
        CP_COMMIT();
    };

    const int lane = tid & 31, wid = tid >> 5;
    const int wm = (wid & 1) * 64;
    const int wn = (wid >> 1) * 24;

    const int msel   = lane >> 3;
    const int arow_f = (msel & 1) * 8 + (lane & 7);
    const int akoff  = (msel >> 1) * 8;
    const int brow_f = (msel >> 1) * 8 + (lane & 7);
    const int bkoff  = (msel & 1) * 8;
    const int l2     = lane & 15;
    const int b2row  = 16 + (l2 & 7);
    const int b2koff = ((l2 >> 3) & 1) * 8;

    float acc[4][3][4];
    #pragma unroll
    for (int mt = 0; mt < 4; mt++)
        #pragma unroll
        for (int nb = 0; nb < 3; nb++)
            #pragma unroll
            for (int r = 0; r < 4; r++) acc[mt][nb][r] = 0.f;

    issue(0, 0);
    issue(32, 1);

    #pragma unroll 1
    for (int c = 0; c < NCH; ++c) {
        asm volatile("cp.async.wait_group 1;" ::: "memory");
        __syncthreads();
        uint32_t sA = sbase + (c & 1) * GBUF;

        #pragma unroll
        for (int ks = 0; ks < 32; ks += 16) {
            uint32_t ah[4][4], bw[3][2];
            uint32_t al[4][4];
            {
                uint32_t bd = sA + OFF_B + (wn + brow_f) * 80 + (ks + bkoff) * 2;
                ldsm4(bw[0][0], bw[0][1], bw[1][0], bw[1][1], bd);
                uint32_t bd2 = sA + OFF_B + (wn + b2row) * 80 + (ks + b2koff) * 2;
                ldsm2(bw[2][0], bw[2][1], bd2);
            }
            #pragma unroll
            for (int mt = 0; mt < 4; mt++) {
                uint32_t ad = sA + (wm + mt * 16 + arow_f) * 80 + (ks + akoff) * 2;
                ldsm4(ah[mt][0], ah[mt][1], ah[mt][2], ah[mt][3], ad);
                if (L0) ldsm4(al[mt][0], al[mt][1], al[mt][2], al[mt][3], ad + OFF_AL);
            }
            #pragma unroll
            for (int mt = 0; mt < 4; mt++)
                #pragma unroll
                for (int nb = 0; nb < 3; nb++) {
                    mma16816h(acc[mt][nb], ah[mt], bw[nb]);
                    if (L0) mma16816h(acc[mt][nb], al[mt], bw[nb]);
                }
        }
        __syncthreads();
        if (c + 2 < NCH) issue((c + 2) * 32, c & 1);
        else             CP_COMMIT();          // keep wait count uniform
    }

    float* sC = (float*)smem;
    #pragma unroll
    for (int mt = 0; mt < 4; mt++)
        #pragma unroll
        for (int nb = 0; nb < 3; nb++) {
            int r = wm + mt * 16 + (lane >> 2);
            int cc = wn + nb * 8 + (lane & 3) * 2;
            sC[r * 100 + cc]           = acc[mt][nb][0];
            sC[r * 100 + cc + 1]       = acc[mt][nb][1];
            sC[(r + 8) * 100 + cc]     = acc[mt][nb][2];
            sC[(r + 8) * 100 + cc + 1] = acc[mt][nb][3];
        }
    __syncthreads();

    #pragma unroll
    for (int t = 0; t < 16; t++) {
        int idx = t * 256 + tid;
        int r = idx >> 5, j = idx & 31;
        float iv = sC[r * 100 + 3 * j + 0] + gc[n0 + 3 * j + 0];
        float gv = sC[r * 100 + 3 * j + 1] + gc[n0 + 3 * j + 1];
        float ov = sC[r * 100 + 3 * j + 2] + gc[n0 + 3 * j + 2];
        float cv = (1.f / (1.f + expf(-iv))) * tanhf(gv);
        float hv = (1.f / (1.f + expf(-ov))) * tanhf(cv);
        size_t o = (size_t)(m0 + r) * 512 + (size_t)(n0 / 3 + j);
        if (L0) {
            g_h1h[o] = __float2half(hv);
        } else {
            g_h2[o] = hv;
        }
    }
}

// ---------------- FC ----------------
__global__ __launch_bounds__(256)
void fc_kernel(const float* __restrict__ fcw, const float* __restrict__ fcb,
               float* __restrict__ e, int nrows) {
    __shared__ float w0[512], w1[512];
    for (int i = threadIdx.x; i < 512; i += blockDim.x) {
        w0[i] = fcw[i];
        w1[i] = fcw[512 + i];
    }
    __syncthreads();
    int warp = (int)((blockIdx.x * (size_t)blockDim.x + threadIdx.x) >> 5);
    int lane = threadIdx.x & 31;
    if (warp >= nrows) return;
    const float* h = g_h2 + (size_t)warp * 512;
    float s0 = 0.f, s1 = 0.f;
    #pragma unroll
    for (int k = lane * 4; k < 512; k += 128) {
        float4 hv = *(const float4*)(h + k);
        s0 += hv.x * w0[k] + hv.y * w0[k + 1] + hv.z * w0[k + 2] + hv.w * w0[k + 3];
        s1 += hv.x * w1[k] + hv.y * w1[k + 1] + hv.z * w1[k + 2] + hv.w * w1[k + 3];
    }
    #pragma unroll
    for (int o = 16; o; o >>= 1) {
        s0 += __shfl_down_sync(0xffffffffu, s0, o);
        s1 += __shfl_down_sync(0xffffffffu, s1, o);
    }
    if (!lane) {
        e[(size_t)warp * 2 + 0] = s0 + fcb[0];
        e[(size_t)warp * 2 + 1] = s1 + fcb[1];
    }
}

// ---------------- CRF NLL: parallel log-semiring reduce ----------------------
__device__ __forceinline__ double lse2(double a, double b) {
    double m = fmax(a, b), n = fmin(a, b);
    return m + log1p(exp(n - m));
}

__global__ __launch_bounds__(256)
void crf_part(const float* __restrict__ e, const int* __restrict__ tags,
              const float* __restrict__ trans, int N) {
    __shared__ double sP[256][4];
    __shared__ double sN[256];
    const int t = threadIdx.x;
    const long n = (long)blockIdx.x * 256 + t;
    const double T00 = trans[0], T01 = trans[1], T10 = trans[2], T11 = trans[3];
    const double NEG = -1e30;

    double m00 = 0.0, m01 = NEG, m10 = NEG, m11 = 0.0;
    double np = 0.0;
    if (n < N) {
        int tg = tags[n];
        np = (double)e[n * 2 + tg];
        if (n >= 1) {
            int tp = tags[n - 1];
            np += (tp == 0) ? (tg == 0 ? T00 : T01) : (tg == 0 ? T10 : T11);
            double e0 = (double)e[n * 2 + 0];
            double e1 = (double)e[n * 2 + 1];
            m00 = T00 + e0; m01 = T01 + e1;
            m10 = T10 + e0; m11 = T11 + e1;
        }
    }
    sP[t][0] = m00; sP[t][1] = m01; sP[t][2] = m10; sP[t][3] = m11;
    sN[t] = np;
    __syncthreads();

    for (int half = 128; half >= 1; half >>= 1) {
        double a0, a1, a2, a3, b0, b1, b2, b3, nn;
        bool act = t < half;
        if (act) {
            a0 = sP[2 * t][0];     a1 = sP[2 * t][1];
            a2 = sP[2 * t][2];     a3 = sP[2 * t][3];
            b0 = sP[2 * t + 1][0]; b1 = sP[2 * t + 1][1];
            b2 = sP[2 * t + 1][2]; b3 = sP[2 * t + 1][3];
            nn = sN[2 * t] + sN[2 * t + 1];
        }
        __syncthreads();
        if (act) {
            sP[t][0] = lse2(a0 + b0, a1 + b2);
            sP[t][1] = lse2(a0 + b1, a1 + b3);
            sP[t][2] = lse2(a2 + b0, a3 + b2);
            sP[t][3] = lse2(a2 + b1, a3 + b3);
            sN[t] = nn;
        }
        __syncthreads();
    }
    if (t == 0) {
        g_crfP[blockIdx.x][0] = sP[0][0];
        g_crfP[blockIdx.x][1] = sP[0][1];
        g_crfP[blockIdx.x][2] = sP[0][2];
        g_crfP[blockIdx.x][3] = sP[0][3];
        g_crfN[blockIdx.x] = sN[0];
    }
}

__global__ __launch_bounds__(256)
void crf_comb(const float* __restrict__ e, const int* __restrict__ tags,
              const float* __restrict__ startv, const float* __restrict__ endv,
              float* __restrict__ loss_out, int N, int nb) {
    __shared__ double sP[256][4];
    __shared__ double sN[256];
    const int t = threadIdx.x;
    const double NEG = -1e30;
    if (t < nb) {
        sP[t][0] = g_crfP[t][0]; sP[t][1] = g_crfP[t][1];
        sP[t][2] = g_crfP[t][2]; sP[t][3] = g_crfP[t][3];
        sN[t] = g_crfN[t];
    } else {
        sP[t][0] = 0.0; sP[t][1] = NEG; sP[t][2] = NEG; sP[t][3] = 0.0;
        sN[t] = 0.0;
    }
    __syncthreads();

    for (int half = 128; half >= 1; half >>= 1) {
        double a0, a1, a2, a3, b0, b1, b2, b3, nn;
        bool act = t < half;
        if (act) {
            a0 = sP[2 * t][0];     a1 = sP[2 * t][1];
            a2 = sP[2 * t][2];     a3 = sP[2 * t][3];
            b0 = sP[2 * t + 1][0]; b1 = sP[2 * t + 1][1];
            b2 = sP[2 * t + 1][2]; b3 = sP[2 * t + 1][3];
            nn = sN[2 * t] + sN[2 * t + 1];
        }
        __syncthreads();
        if (act) {
            sP[t][0] = lse2(a0 + b0, a1 + b2);
            sP[t][1] = lse2(a0 + b1, a1 + b3);
            sP[t][2] = lse2(a2 + b0, a3 + b2);
            sP[t][3] = lse2(a2 + b1, a3 + b3);
            sN[t] = nn;
        }
        __syncthreads();
    }

    if (t == 0) {
        double num = sN[0] + (double)startv[tags[0]] + (double)endv[tags[N - 1]];
        double a0 = (double)startv[0] + (double)e[0];
        double a1 = (double)startv[1] + (double)e[1];
        double f0 = lse2(a0 + sP[0][0], a1 + sP[0][2]);
        double f1 = lse2(a0 + sP[0][1], a1 + sP[0][3]);
        double den = lse2(f0 + (double)endv[0], f1 + (double)endv[1]);
        loss_out[0] = (float)(den - num);
    }
}

// ---------------- launch ----------------
extern "C" void kernel_launch(void* const* d_in, const int* in_sizes, int n_in,
                              void* d_out, int out_size) {
    const float* x        = (const float*)d_in[0];
    const float* gamma    = (const float*)d_in[1];
    const float* beta     = (const float*)d_in[2];
    const float* w_ih_l0  = (const float*)d_in[3];
    const float* b_ih_l0  = (const float*)d_in[5];
    const float* b_hh_l0  = (const float*)d_in[6];
    const float* w_ih_l1  = (const float*)d_in[7];
    const float* b_ih_l1  = (const float*)d_in[9];
    const float* b_hh_l1  = (const float*)d_in[10];
    const float* fc_w     = (const float*)d_in[11];
    const float* fc_b     = (const float*)d_in[12];
    const float* crf_start= (const float*)d_in[13];
    const float* crf_end  = (const float*)d_in[14];
    const float* crf_trans= (const float*)d_in[15];
    const int*   labels   = (const int*)d_in[16];

    int N = in_sizes[0] / 768;      // 65536
    float* out = (float*)d_out;
    float* e = out + 1;

    cudaFuncSetAttribute((const void*)gemm_lstm_tc<true>,
                         cudaFuncAttributeMaxDynamicSharedMemorySize, SMEM0);
    cudaFuncSetAttribute((const void*)gemm_lstm_tc<false>,
                         cudaFuncAttributeMaxDynamicSharedMemorySize, SMEM1);

    int rpb = (N + 127) / 128;
    int nblk = (N + rpb - 1) / rpb;
    int nsplit = N * 768 / 4 / 256;                        // 49152

    stats_kernel<<<nblk, 768>>>(x, rpb, N);                                    // 0
    prep_kernel<<<1, 768>>>(gamma, beta, N, nblk);                             // 1
    prep_all_l0<<<nsplit + 4608 + 192, 256>>>((const float4*)x, w_ih_l0,
                                              b_ih_l0, b_hh_l0, nsplit);       // 2
    dim3 gg(16, N / 128);
    gemm_lstm_tc<true ><<<gg, 256, SMEM0>>>();                                 // 3  <- ncu
    prep_l1<<<3078, 256>>>(w_ih_l1, b_ih_l1, b_hh_l1);                         // 4
    gemm_lstm_tc<false><<<gg, 256, SMEM1>>>();                                 // 5
    fc_kernel<<<(N / 8), 256>>>(fc_w, fc_b, e, N);                             // 6
    crf_part<<<(N + 255) / 256, 256>>>(e, labels, crf_trans, N);               // 7
    crf_comb<<<1, 256>>>(e, labels, crf_start, crf_end, out, N, (N + 255) / 256); // 8
}

// round 13
// speedup vs baseline: 4.8210x; 1.2695x over previous
#include <cuda_runtime.h>
#include <cuda_fp16.h>
#include <math.h>
#include <stdint.h>

#define NROWS 65536

// ---------------- scratch (device globals; no allocation allowed) ----------
__device__ float  g_psum[128 * 768];
__device__ float  g_psumsq[128 * 768];
__device__ float  g_scale[768];
__device__ float  g_shift[768];
__device__ __half g_xh[(size_t)NROWS * 768];
__device__ __half g_W0[1536 * 768];
__device__ __half g_W1[1536 * 512];
__device__ __half g_h1h[(size_t)NROWS * 512];
__device__ float g_h2[(size_t)NROWS * 512];
__device__ float g_gc0[1536];
__device__ float g_gc1[1536];
__device__ double g_crfP[256][4];
__device__ double g_crfN[256];

// ---------------- helpers ----------------
__device__ __forceinline__ void cpasync16(uint32_t dst, const void* src) {
    asm volatile("cp.async.cg.shared.global [%0], [%1], 16;" :: "r"(dst), "l"(src));
}
#define CP_COMMIT() asm volatile("cp.async.commit_group;")

__device__ __forceinline__ void ldsm4(uint32_t& r0, uint32_t& r1, uint32_t& r2,
                                      uint32_t& r3, uint32_t addr) {
    asm volatile("ldmatrix.sync.aligned.m8n8.x4.shared.b16 {%0,%1,%2,%3}, [%4];"
                 : "=r"(r0), "=r"(r1), "=r"(r2), "=r"(r3) : "r"(addr));
}
__device__ __forceinline__ void ldsm2(uint32_t& r0, uint32_t& r1, uint32_t addr) {
    asm volatile("ldmatrix.sync.aligned.m8n8.x2.shared.b16 {%0,%1}, [%2];"
                 : "=r"(r0), "=r"(r1) : "r"(addr));
}
__device__ __forceinline__ void mma16816h(float* c, const uint32_t* a, const uint32_t* b) {
    asm volatile("mma.sync.aligned.m16n8k16.row.col.f32.f16.f16.f32 "
                 "{%0,%1,%2,%3}, {%4,%5,%6,%7}, {%8,%9}, {%0,%1,%2,%3};"
                 : "+f"(c[0]), "+f"(c[1]), "+f"(c[2]), "+f"(c[3])
                 : "r"(a[0]), "r"(a[1]), "r"(a[2]), "r"(a[3]), "r"(b[0]), "r"(b[1]));
}

// ---------------- BN stats (per-block partials) -----------------------------
__global__ void stats_kernel(const float* __restrict__ x, int rowsPerBlock, int nrows) {
    int c = threadIdx.x;
    int b = blockIdx.x;
    long r0 = (long)b * rowsPerBlock;
    float s = 0.f, s2 = 0.f;
    for (int r = 0; r < rowsPerBlock; ++r) {
        long row = r0 + r;
        if (row < nrows) {
            float v = x[row * 768 + c];
            s += v; s2 += v * v;
        }
    }
    g_psum[b * 768 + c] = s;
    g_psumsq[b * 768 + c] = s2;
}

__global__ void prep_kernel(const float* __restrict__ gamma,
                            const float* __restrict__ beta, int nrows, int nblk) {
    int c = threadIdx.x;
    double s = 0.0, s2 = 0.0;
    for (int b = 0; b < nblk; ++b) {
        s  += (double)g_psum[b * 768 + c];
        s2 += (double)g_psumsq[b * 768 + c];
    }
    double mean = s / (double)nrows;
    double var  = s2 / (double)nrows - mean * mean;
    float sc = gamma[c] * (float)(1.0 / sqrt(var + 1e-5));
    g_scale[c] = sc;
    g_shift[c] = beta[c] - (float)mean * sc;
}

// ------------- merged L0 prep: split_x(fp16) + repackW0(fp16) + gconst0 ------
__global__ void prep_all_l0(const float4* __restrict__ x4,
                            const float* __restrict__ w,
                            const float* __restrict__ bih,
                            const float* __restrict__ bhh,
                            int nsplit) {
    int bid = blockIdx.x;
    int tid = threadIdx.x;
    if (bid < nsplit) {
        size_t i = (size_t)bid * 256 + tid;
        float4 v = x4[i];
        int c = (int)(i % 192) * 4;
        v.x *= g_scale[c + 0]; v.y *= g_scale[c + 1];
        v.z *= g_scale[c + 2]; v.w *= g_scale[c + 3];
        __half2* ph = (__half2*)g_xh;
        ph[i * 2 + 0] = __halves2half2(__float2half(v.x), __float2half(v.y));
        ph[i * 2 + 1] = __halves2half2(__float2half(v.z), __float2half(v.w));
    } else if (bid < nsplit + 4608) {
        int idx = (bid - nsplit) * 256 + tid;      // < 1536*768
        int d = idx % 768;
        int n = idx / 768;
        int g = n % 3, j = n / 3;
        int dir = j >> 8, jj = j & 255;
        int grow = (g == 0) ? jj : (g == 1 ? 512 + jj : 768 + jj);
        float v = w[(size_t)(dir * 1024 + grow) * 768 + d];
        g_W0[idx] = __float2half(v);
    } else {
        int warpId = (bid - nsplit - 4608) * 8 + (tid >> 5);   // < 1536
        int lane = tid & 31;
        int g = warpId % 3, j = warpId / 3;
        int dir = j >> 8, jj = j & 255;
        int grow = (g == 0) ? jj : (g == 1 ? 512 + jj : 768 + jj);
        const float* wr = w + (size_t)(dir * 1024 + grow) * 768;
        float s = 0.f;
        for (int k = lane; k < 768; k += 32) s += g_shift[k] * wr[k];
        #pragma unroll
        for (int o = 16; o; o >>= 1) s += __shfl_down_sync(0xffffffffu, s, o);
        if (!lane) g_gc0[warpId] = s + bih[dir * 1024 + grow] + bhh[dir * 1024 + grow];
    }
}

// ------------- merged L1 prep: repackW1(fp16) + gconst1 ----------------------
__global__ void prep_l1(const float* __restrict__ w,
                        const float* __restrict__ bih,
                        const float* __restrict__ bhh) {
    int bid = blockIdx.x;
    int tid = threadIdx.x;
    if (bid < 3072) {
        int idx = bid * 256 + tid;                 // < 1536*512
        int d = idx % 512;
        int n = idx / 512;
        int g = n % 3, j = n / 3;
        int dir = j >> 8, jj = j & 255;
        int grow = (g == 0) ? jj : (g == 1 ? 512 + jj : 768 + jj);
        float v = w[(size_t)(dir * 1024 + grow) * 512 + d];
        g_W1[idx] = __float2half(v);
    } else {
        int n = (bid - 3072) * 256 + tid;
        if (n >= 1536) return;
        int g = n % 3, j = n / 3;
        int dir = j >> 8, jj = j & 255;
        int grow = (g == 0) ? jj : (g == 1 ? 512 + jj : 768 + jj);
        g_gc1[n] = bih[dir * 1024 + grow] + bhh[dir * 1024 + grow];
    }
}

// ---------------- HMMA GEMM + fused LSTM epilogue ---------------------------
// CTA 128 rows x 96 gate cols, 8 warps (2M x 4N), warp 64x24.
// Single fp16 product both layers: acc += X*W. 2-stage pipeline, 3 CTAs/SM.
// Stage: A 128x80B=10240 + B 96x80B=7680 -> GBUF=17920.
#define GBUF   17920
#define OFF_B  10240
#define SMEM_TC 51200    // max(2*GBUF=35840, epilogue 128*100*4=51200)

template <bool L0>
__global__ void __launch_bounds__(256, 3) gemm_lstm_tc() {
    constexpr int K = L0 ? 768 : 512;
    constexpr int NCH = K / 32;
    const __half* __restrict__ Ah = L0 ? g_xh : g_h1h;
    const __half* __restrict__ Bw = L0 ? g_W0 : g_W1;
    const float* __restrict__ gc = L0 ? g_gc0 : g_gc1;

    extern __shared__ char smem[];
    uint32_t sbase = (uint32_t)__cvta_generic_to_shared(smem);

    const int tid = threadIdx.x;
    const int m0 = blockIdx.y * 128;
    const int n0 = blockIdx.x * 96;

    auto issue = [&](int kt, int b) {
        uint32_t sA = sbase + b * GBUF;
        #pragma unroll
        for (int it = 0; it < 2; ++it) {   // A: 128 rows x 4 x16B = 512 transfers
            int idx = tid + it * 256;
            int r = idx >> 2, q = idx & 3;
            uint32_t d = sA + r * 80 + q * 16;
            const size_t go = (size_t)(m0 + r) * K + kt + q * 8;
            cpasync16(d, Ah + go);
        }
        {   // B: 96 rows x 4 x16B = 384 transfers on 256 threads
            int r = tid >> 2, q = tid & 3;             // rows 0..63
            uint32_t d = sA + OFF_B + r * 80 + q * 16;
            const size_t go = (size_t)(n0 + r) * K + kt + q * 8;
            cpasync16(d, Bw + go);
            if (tid < 128) {                           // rows 64..95
                int r2 = 64 + (tid >> 2), q2 = tid & 3;
                uint32_t d2 = sA + OFF_B + r2 * 80 + q2 * 16;
                const size_t go2 = (size_t)(n0 + r2) * K + kt + q2 * 8;
                cpasync16(d2, Bw + go2);
            }
        }
        CP_COMMIT();
    };

    const int lane = tid & 31, wid = tid >> 5;
    const int wm = (wid & 1) * 64;
    const int wn = (wid >> 1) * 24;

    const int msel   = lane >> 3;
    const int arow_f = (msel & 1) * 8 + (lane & 7);
    const int akoff  = (msel >> 1) * 8;
    const int brow_f = (msel >> 1) * 8 + (lane & 7);
    const int bkoff  = (msel & 1) * 8;
    const int l2     = lane & 15;
    const int b2row  = 16 + (l2 & 7);
    const int b2koff = ((l2 >> 3) & 1) * 8;

    float acc[4][3][4];
    #pragma unroll
    for (int mt = 0; mt < 4; mt++)
        #pragma unroll
        for (int nb = 0; nb < 3; nb++)
            #pragma unroll
            for (int r = 0; r < 4; r++) acc[mt][nb][r] = 0.f;

    issue(0, 0);
    issue(32, 1);

    #pragma unroll 1
    for (int c = 0; c < NCH; ++c) {
        asm volatile("cp.async.wait_group 1;" ::: "memory");
        __syncthreads();
        uint32_t sA = sbase + (c & 1) * GBUF;

        #pragma unroll
        for (int ks = 0; ks < 32; ks += 16) {
            uint32_t ah[4][4], bw[3][2];
            {
                uint32_t bd = sA + OFF_B + (wn + brow_f) * 80 + (ks + bkoff) * 2;
                ldsm4(bw[0][0], bw[0][1], bw[1][0], bw[1][1], bd);
                uint32_t bd2 = sA + OFF_B + (wn + b2row) * 80 + (ks + b2koff) * 2;
                ldsm2(bw[2][0], bw[2][1], bd2);
            }
            #pragma unroll
            for (int mt = 0; mt < 4; mt++) {
                uint32_t ad = sA + (wm + mt * 16 + arow_f) * 80 + (ks + akoff) * 2;
                ldsm4(ah[mt][0], ah[mt][1], ah[mt][2], ah[mt][3], ad);
            }
            #pragma unroll
            for (int mt = 0; mt < 4; mt++)
                #pragma unroll
                for (int nb = 0; nb < 3; nb++)
                    mma16816h(acc[mt][nb], ah[mt], bw[nb]);
        }
        __syncthreads();
        if (c + 2 < NCH) issue((c + 2) * 32, c & 1);
        else             CP_COMMIT();          // keep wait count uniform
    }

    float* sC = (float*)smem;
    #pragma unroll
    for (int mt = 0; mt < 4; mt++)
        #pragma unroll
        for (int nb = 0; nb < 3; nb++) {
            int r = wm + mt * 16 + (lane >> 2);
            int cc = wn + nb * 8 + (lane & 3) * 2;
            sC[r * 100 + cc]           = acc[mt][nb][0];
            sC[r * 100 + cc + 1]       = acc[mt][nb][1];
            sC[(r + 8) * 100 + cc]     = acc[mt][nb][2];
            sC[(r + 8) * 100 + cc + 1] = acc[mt][nb][3];
        }
    __syncthreads();

    #pragma unroll
    for (int t = 0; t < 16; t++) {
        int idx = t * 256 + tid;
        int r = idx >> 5, j = idx & 31;
        float iv = sC[r * 100 + 3 * j + 0] + gc[n0 + 3 * j + 0];
        float gv = sC[r * 100 + 3 * j + 1] + gc[n0 + 3 * j + 1];
        float ov = sC[r * 100 + 3 * j + 2] + gc[n0 + 3 * j + 2];
        float cv = (1.f / (1.f + expf(-iv))) * tanhf(gv);
        float hv = (1.f / (1.f + expf(-ov))) * tanhf(cv);
        size_t o = (size_t)(m0 + r) * 512 + (size_t)(n0 / 3 + j);
        if (L0) {
            g_h1h[o] = __float2half(hv);
        } else {
            g_h2[o] = hv;
        }
    }
}

// ---------------- FC ----------------
__global__ __launch_bounds__(256)
void fc_kernel(const float* __restrict__ fcw, const float* __restrict__ fcb,
               float* __restrict__ e, int nrows) {
    __shared__ float w0[512], w1[512];
    for (int i = threadIdx.x; i < 512; i += blockDim.x) {
        w0[i] = fcw[i];
        w1[i] = fcw[512 + i];
    }
    __syncthreads();
    int warp = (int)((blockIdx.x * (size_t)blockDim.x + threadIdx.x) >> 5);
    int lane = threadIdx.x & 31;
    if (warp >= nrows) return;
    const float* h = g_h2 + (size_t)warp * 512;
    float s0 = 0.f, s1 = 0.f;
    #pragma unroll
    for (int k = lane * 4; k < 512; k += 128) {
        float4 hv = *(const float4*)(h + k);
        s0 += hv.x * w0[k] + hv.y * w0[k + 1] + hv.z * w0[k + 2] + hv.w * w0[k + 3];
        s1 += hv.x * w1[k] + hv.y * w1[k + 1] + hv.z * w1[k + 2] + hv.w * w1[k + 3];
    }
    #pragma unroll
    for (int o = 16; o; o >>= 1) {
        s0 += __shfl_down_sync(0xffffffffu, s0, o);
        s1 += __shfl_down_sync(0xffffffffu, s1, o);
    }
    if (!lane) {
        e[(size_t)warp * 2 + 0] = s0 + fcb[0];
        e[(size_t)warp * 2 + 1] = s1 + fcb[1];
    }
}

// ---------------- CRF NLL: parallel log-semiring reduce ----------------------
__device__ __forceinline__ double lse2(double a, double b) {
    double m = fmax(a, b), n = fmin(a, b);
    return m + log1p(exp(n - m));
}

__global__ __launch_bounds__(256)
void crf_part(const float* __restrict__ e, const int* __restrict__ tags,
              const float* __restrict__ trans, int N) {
    __shared__ double sP[256][4];
    __shared__ double sN[256];
    const int t = threadIdx.x;
    const long n = (long)blockIdx.x * 256 + t;
    const double T00 = trans[0], T01 = trans[1], T10 = trans[2], T11 = trans[3];
    const double NEG = -1e30;

    double m00 = 0.0, m01 = NEG, m10 = NEG, m11 = 0.0;
    double np = 0.0;
    if (n < N) {
        int tg = tags[n];
        np = (double)e[n * 2 + tg];
        if (n >= 1) {
            int tp = tags[n - 1];
            np += (tp == 0) ? (tg == 0 ? T00 : T01) : (tg == 0 ? T10 : T11);
            double e0 = (double)e[n * 2 + 0];
            double e1 = (double)e[n * 2 + 1];
            m00 = T00 + e0; m01 = T01 + e1;
            m10 = T10 + e0; m11 = T11 + e1;
        }
    }
    sP[t][0] = m00; sP[t][1] = m01; sP[t][2] = m10; sP[t][3] = m11;
    sN[t] = np;
    __syncthreads();

    for (int half = 128; half >= 1; half >>= 1) {
        double a0, a1, a2, a3, b0, b1, b2, b3, nn;
        bool act = t < half;
        if (act) {
            a0 = sP[2 * t][0];     a1 = sP[2 * t][1];
            a2 = sP[2 * t][2];     a3 = sP[2 * t][3];
            b0 = sP[2 * t + 1][0]; b1 = sP[2 * t + 1][1];
            b2 = sP[2 * t + 1][2]; b3 = sP[2 * t + 1][3];
            nn = sN[2 * t] + sN[2 * t + 1];
        }
        __syncthreads();
        if (act) {
            sP[t][0] = lse2(a0 + b0, a1 + b2);
            sP[t][1] = lse2(a0 + b1, a1 + b3);
            sP[t][2] = lse2(a2 + b0, a3 + b2);
            sP[t][3] = lse2(a2 + b1, a3 + b3);
            sN[t] = nn;
        }
        __syncthreads();
    }
    if (t == 0) {
        g_crfP[blockIdx.x][0] = sP[0][0];
        g_crfP[blockIdx.x][1] = sP[0][1];
        g_crfP[blockIdx.x][2] = sP[0][2];
        g_crfP[blockIdx.x][3] = sP[0][3];
        g_crfN[blockIdx.x] = sN[0];
    }
}

__global__ __launch_bounds__(256)
void crf_comb(const float* __restrict__ e, const int* __restrict__ tags,
              const float* __restrict__ startv, const float* __restrict__ endv,
              float* __restrict__ loss_out, int N, int nb) {
    __shared__ double sP[256][4];
    __shared__ double sN[256];
    const int t = threadIdx.x;
    const double NEG = -1e30;
    if (t < nb) {
        sP[t][0] = g_crfP[t][0]; sP[t][1] = g_crfP[t][1];
        sP[t][2] = g_crfP[t][2]; sP[t][3] = g_crfP[t][3];
        sN[t] = g_crfN[t];
    } else {
        sP[t][0] = 0.0; sP[t][1] = NEG; sP[t][2] = NEG; sP[t][3] = 0.0;
        sN[t] = 0.0;
    }
    __syncthreads();

    for (int half = 128; half >= 1; half >>= 1) {
        double a0, a1, a2, a3, b0, b1, b2, b3, nn;
        bool act = t < half;
        if (act) {
            a0 = sP[2 * t][0];     a1 = sP[2 * t][1];
            a2 = sP[2 * t][2];     a3 = sP[2 * t][3];
            b0 = sP[2 * t + 1][0]; b1 = sP[2 * t + 1][1];
            b2 = sP[2 * t + 1][2]; b3 = sP[2 * t + 1][3];
            nn = sN[2 * t] + sN[2 * t + 1];
        }
        __syncthreads();
        if (act) {
            sP[t][0] = lse2(a0 + b0, a1 + b2);
            sP[t][1] = lse2(a0 + b1, a1 + b3);
            sP[t][2] = lse2(a2 + b0, a3 + b2);
            sP[t][3] = lse2(a2 + b1, a3 + b3);
            sN[t] = nn;
        }
        __syncthreads();
    }

    if (t == 0) {
        double num = sN[0] + (double)startv[tags[0]] + (double)endv[tags[N - 1]];
        double a0 = (double)startv[0] + (double)e[0];
        double a1 = (double)startv[1] + (double)e[1];
        double f0 = lse2(a0 + sP[0][0], a1 + sP[0][2]);
        double f1 = lse2(a0 + sP[0][1], a1 + sP[0][3]);
        double den = lse2(f0 + (double)endv[0], f1 + (double)endv[1]);
        loss_out[0] = (float)(den - num);
    }
}

// ---------------- launch ----------------
extern "C" void kernel_launch(void* const* d_in, const int* in_sizes, int n_in,
                              void* d_out, int out_size) {
    const float* x        = (const float*)d_in[0];
    const float* gamma    = (const float*)d_in[1];
    const float* beta     = (const float*)d_in[2];
    const float* w_ih_l0  = (const float*)d_in[3];
    const float* b_ih_l0  = (const float*)d_in[5];
    const float* b_hh_l0  = (const float*)d_in[6];
    const float* w_ih_l1  = (const float*)d_in[7];
    const float* b_ih_l1  = (const float*)d_in[9];
    const float* b_hh_l1  = (const float*)d_in[10];
    const float* fc_w     = (const float*)d_in[11];
    const float* fc_b     = (const float*)d_in[12];
    const float* crf_start= (const float*)d_in[13];
    const float* crf_end  = (const float*)d_in[14];
    const float* crf_trans= (const float*)d_in[15];
    const int*   labels   = (const int*)d_in[16];

    int N = in_sizes[0] / 768;      // 65536
    float* out = (float*)d_out;
    float* e = out + 1;

    cudaFuncSetAttribute((const void*)gemm_lstm_tc<true>,
                         cudaFuncAttributeMaxDynamicSharedMemorySize, SMEM_TC);
    cudaFuncSetAttribute((const void*)gemm_lstm_tc<false>,
                         cudaFuncAttributeMaxDynamicSharedMemorySize, SMEM_TC);

    int rpb = (N + 127) / 128;
    int nblk = (N + rpb - 1) / rpb;
    int nsplit = N * 768 / 4 / 256;                        // 49152

    stats_kernel<<<nblk, 768>>>(x, rpb, N);                                    // 0
    prep_kernel<<<1, 768>>>(gamma, beta, N, nblk);                             // 1
    prep_all_l0<<<nsplit + 4608 + 192, 256>>>((const float4*)x, w_ih_l0,
                                              b_ih_l0, b_hh_l0, nsplit);       // 2
    dim3 gg(16, N / 128);
    gemm_lstm_tc<true ><<<gg, 256, SMEM_TC>>>();                               // 3  <- ncu
    prep_l1<<<3078, 256>>>(w_ih_l1, b_ih_l1, b_hh_l1);                         // 4
    gemm_lstm_tc<false><<<gg, 256, SMEM_TC>>>();                               // 5
    fc_kernel<<<(N / 8), 256>>>(fc_w, fc_b, e, N);                             // 6
    crf_part<<<(N + 255) / 256, 256>>>(e, labels, crf_trans, N);               // 7
    crf_comb<<<1, 256>>>(e, labels, crf_start, crf_end, out, N, (N + 255) / 256); // 8
}

// round 14
// speedup vs baseline: 4.9069x; 1.0178x over previous
#include <cuda_runtime.h>
#include <cuda_fp16.h>
#include <math.h>
#include <stdint.h>

#define NROWS 65536

// ---------------- scratch (device globals; no allocation allowed) ----------
__device__ float  g_psum[128 * 768];
__device__ float  g_psumsq[128 * 768];
__device__ float  g_scale[768];
__device__ float  g_shift[768];
__device__ __half g_xh[(size_t)NROWS * 768];
__device__ __half g_W0[1536 * 768];
__device__ __half g_W1[1536 * 512];
__device__ __half g_h1h[(size_t)NROWS * 512];
__device__ float g_gc0[1536];
__device__ float g_gc1[1536];
__device__ double g_crfP[256][4];
__device__ double g_crfN[256];

// ---------------- helpers ----------------
__device__ __forceinline__ void cpasync16(uint32_t dst, const void* src) {
    asm volatile("cp.async.cg.shared.global [%0], [%1], 16;" :: "r"(dst), "l"(src));
}
#define CP_COMMIT() asm volatile("cp.async.commit_group;")

__device__ __forceinline__ void ldsm4(uint32_t& r0, uint32_t& r1, uint32_t& r2,
                                      uint32_t& r3, uint32_t addr) {
    asm volatile("ldmatrix.sync.aligned.m8n8.x4.shared.b16 {%0,%1,%2,%3}, [%4];"
                 : "=r"(r0), "=r"(r1), "=r"(r2), "=r"(r3) : "r"(addr));
}
__device__ __forceinline__ void mma16816h(float* c, const uint32_t* a, const uint32_t* b) {
    asm volatile("mma.sync.aligned.m16n8k16.row.col.f32.f16.f16.f32 "
                 "{%0,%1,%2,%3}, {%4,%5,%6,%7}, {%8,%9}, {%0,%1,%2,%3};"
                 : "+f"(c[0]), "+f"(c[1]), "+f"(c[2]), "+f"(c[3])
                 : "r"(a[0]), "r"(a[1]), "r"(a[2]), "r"(a[3]), "r"(b[0]), "r"(b[1]));
}

// ---------------- BN stats (per-block partials) -----------------------------
__global__ void stats_kernel(const float* __restrict__ x, int rowsPerBlock, int nrows) {
    int c = threadIdx.x;
    int b = blockIdx.x;
    long r0 = (long)b * rowsPerBlock;
    float s = 0.f, s2 = 0.f;
    for (int r = 0; r < rowsPerBlock; ++r) {
        long row = r0 + r;
        if (row < nrows) {
            float v = x[row * 768 + c];
            s += v; s2 += v * v;
        }
    }
    g_psum[b * 768 + c] = s;
    g_psumsq[b * 768 + c] = s2;
}

__global__ void prep_kernel(const float* __restrict__ gamma,
                            const float* __restrict__ beta, int nrows, int nblk) {
    int c = threadIdx.x;
    double s = 0.0, s2 = 0.0;
    for (int b = 0; b < nblk; ++b) {
        s  += (double)g_psum[b * 768 + c];
        s2 += (double)g_psumsq[b * 768 + c];
    }
    double mean = s / (double)nrows;
    double var  = s2 / (double)nrows - mean * mean;
    float sc = gamma[c] * (float)(1.0 / sqrt(var + 1e-5));
    g_scale[c] = sc;
    g_shift[c] = beta[c] - (float)mean * sc;
}

// ------------- merged L0 prep: split_x(fp16) + repackW0(fp16) + gconst0 ------
__global__ void prep_all_l0(const float4* __restrict__ x4,
                            const float* __restrict__ w,
                            const float* __restrict__ bih,
                            const float* __restrict__ bhh,
                            int nsplit) {
    int bid = blockIdx.x;
    int tid = threadIdx.x;
    if (bid < nsplit) {
        size_t i = (size_t)bid * 256 + tid;
        float4 v = x4[i];
        int c = (int)(i % 192) * 4;
        v.x *= g_scale[c + 0]; v.y *= g_scale[c + 1];
        v.z *= g_scale[c + 2]; v.w *= g_scale[c + 3];
        __half2* ph = (__half2*)g_xh;
        ph[i * 2 + 0] = __halves2half2(__float2half(v.x), __float2half(v.y));
        ph[i * 2 + 1] = __halves2half2(__float2half(v.z), __float2half(v.w));
    } else if (bid < nsplit + 4608) {
        int idx = (bid - nsplit) * 256 + tid;      // < 1536*768
        int d = idx % 768;
        int n = idx / 768;
        int g = n % 3, j = n / 3;
        int dir = j >> 8, jj = j & 255;
        int grow = (g == 0) ? jj : (g == 1 ? 512 + jj : 768 + jj);
        float v = w[(size_t)(dir * 1024 + grow) * 768 + d];
        g_W0[idx] = __float2half(v);
    } else {
        int warpId = (bid - nsplit - 4608) * 8 + (tid >> 5);   // < 1536
        int lane = tid & 31;
        int g = warpId % 3, j = warpId / 3;
        int dir = j >> 8, jj = j & 255;
        int grow = (g == 0) ? jj : (g == 1 ? 512 + jj : 768 + jj);
        const float* wr = w + (size_t)(dir * 1024 + grow) * 768;
        float s = 0.f;
        for (int k = lane; k < 768; k += 32) s += g_shift[k] * wr[k];
        #pragma unroll
        for (int o = 16; o; o >>= 1) s += __shfl_down_sync(0xffffffffu, s, o);
        if (!lane) g_gc0[warpId] = s + bih[dir * 1024 + grow] + bhh[dir * 1024 + grow];
    }
}

// ------------- merged L1 prep: repackW1(fp16) + gconst1 + e-bias init --------
__global__ void prep_l1(const float* __restrict__ w,
                        const float* __restrict__ bih,
                        const float* __restrict__ bhh,
                        const float* __restrict__ fcb,
                        float* __restrict__ e, int nrows) {
    int bid = blockIdx.x;
    int tid = threadIdx.x;
    if (bid < 3072) {
        int idx = bid * 256 + tid;                 // < 1536*512
        int d = idx % 512;
        int n = idx / 512;
        int g = n % 3, j = n / 3;
        int dir = j >> 8, jj = j & 255;
        int grow = (g == 0) ? jj : (g == 1 ? 512 + jj : 768 + jj);
        float v = w[(size_t)(dir * 1024 + grow) * 512 + d];
        g_W1[idx] = __float2half(v);
    } else if (bid < 3078) {
        int n = (bid - 3072) * 256 + tid;
        if (n >= 1536) return;
        int g = n % 3, j = n / 3;
        int dir = j >> 8, jj = j & 255;
        int grow = (g == 0) ? jj : (g == 1 ? 512 + jj : 768 + jj);
        g_gc1[n] = bih[dir * 1024 + grow] + bhh[dir * 1024 + grow];
    } else {
        int row = (bid - 3078) * 256 + tid;        // e bias init
        if (row < nrows) {
            e[(size_t)row * 2 + 0] = fcb[0];
            e[(size_t)row * 2 + 1] = fcb[1];
        }
    }
}

// ---------------- HMMA GEMM + fused LSTM (+FC for L1) epilogue --------------
// CTA 128 rows x 192 gate cols, 8 warps (2M x 4N), warp 64x48.
// Single fp16 product: acc += X*W. 2-stage pipeline, 2 CTAs/SM.
// Stage: A 128x80B=10240 + B 192x80B=15360 -> GBUF=25600.
#define GBUF   25600
#define OFF_B  10240
#define SMEM_TC 102400   // epilogue [128][200] floats dominates (2*GBUF=51200)

template <bool L0>
__global__ void __launch_bounds__(256, 2) gemm_lstm_tc(
        const float* __restrict__ fcw, float* __restrict__ e) {
    constexpr int K = L0 ? 768 : 512;
    constexpr int NCH = K / 32;
    const __half* __restrict__ Ah = L0 ? g_xh : g_h1h;
    const __half* __restrict__ Bw = L0 ? g_W0 : g_W1;
    const float* __restrict__ gc = L0 ? g_gc0 : g_gc1;

    extern __shared__ char smem[];
    uint32_t sbase = (uint32_t)__cvta_generic_to_shared(smem);

    const int tid = threadIdx.x;
    const int m0 = blockIdx.y * 128;
    const int n0 = blockIdx.x * 192;

    auto issue = [&](int kt, int b) {
        uint32_t sA = sbase + b * GBUF;
        #pragma unroll
        for (int it = 0; it < 2; ++it) {   // A: 128 rows x 4 x16B = 512 transfers
            int idx = tid + it * 256;
            int r = idx >> 2, q = idx & 3;
            uint32_t d = sA + r * 80 + q * 16;
            const size_t go = (size_t)(m0 + r) * K + kt + q * 8;
            cpasync16(d, Ah + go);
        }
        #pragma unroll
        for (int it = 0; it < 3; ++it) {   // B: 192 rows x 4 x16B = 768 transfers
            int idx = tid + it * 256;
            int r = idx >> 2, q = idx & 3;
            uint32_t d = sA + OFF_B + r * 80 + q * 16;
            const size_t go = (size_t)(n0 + r) * K + kt + q * 8;
            cpasync16(d, Bw + go);
        }
        CP_COMMIT();
    };

    const int lane = tid & 31, wid = tid >> 5;
    const int wm = (wid & 1) * 64;
    const int wn = (wid >> 1) * 48;

    const int msel   = lane >> 3;
    const int arow_f = (msel & 1) * 8 + (lane & 7);
    const int akoff  = (msel >> 1) * 8;
    const int brow_f = (msel >> 1) * 8 + (lane & 7);
    const int bkoff  = (msel & 1) * 8;

    float acc[4][6][4];
    #pragma unroll
    for (int mt = 0; mt < 4; mt++)
        #pragma unroll
        for (int nb = 0; nb < 6; nb++)
            #pragma unroll
            for (int r = 0; r < 4; r++) acc[mt][nb][r] = 0.f;

    issue(0, 0);
    issue(32, 1);

    #pragma unroll 1
    for (int c = 0; c < NCH; ++c) {
        asm volatile("cp.async.wait_group 1;" ::: "memory");
        __syncthreads();
        uint32_t sA = sbase + (c & 1) * GBUF;

        #pragma unroll
        for (int ks = 0; ks < 32; ks += 16) {
            uint32_t bw[6][2];
            #pragma unroll
            for (int p = 0; p < 3; p++) {
                uint32_t bd = sA + OFF_B + (wn + p * 16 + brow_f) * 80 + (ks + bkoff) * 2;
                ldsm4(bw[2 * p][0], bw[2 * p][1], bw[2 * p + 1][0], bw[2 * p + 1][1], bd);
            }
            #pragma unroll
            for (int mt = 0; mt < 4; mt++) {
                uint32_t ah[4];
                uint32_t ad = sA + (wm + mt * 16 + arow_f) * 80 + (ks + akoff) * 2;
                ldsm4(ah[0], ah[1], ah[2], ah[3], ad);
                #pragma unroll
                for (int nb = 0; nb < 6; nb++)
                    mma16816h(acc[mt][nb], ah, bw[nb]);
            }
        }
        __syncthreads();
        if (c + 2 < NCH) issue((c + 2) * 32, c & 1);
        else             CP_COMMIT();          // keep wait count uniform
    }

    float* sC = (float*)smem;
    #pragma unroll
    for (int mt = 0; mt < 4; mt++)
        #pragma unroll
        for (int nb = 0; nb < 6; nb++) {
            int r = wm + mt * 16 + (lane >> 2);
            int cc = wn + nb * 8 + (lane & 3) * 2;
            sC[r * 200 + cc]           = acc[mt][nb][0];
            sC[r * 200 + cc + 1]       = acc[mt][nb][1];
            sC[(r + 8) * 200 + cc]     = acc[mt][nb][2];
            sC[(r + 8) * 200 + cc + 1] = acc[mt][nb][3];
        }
    __syncthreads();

    const int cb = blockIdx.x * 64;
    const int jj = tid & 63;
    float w0 = 0.f, w1 = 0.f;
    if (!L0) {
        w0 = fcw[cb + jj];
        w1 = fcw[512 + cb + jj];
    }

    #pragma unroll
    for (int t = 0; t < 32; t++) {
        int idx = t * 256 + tid;
        int r = idx >> 6, j = idx & 63;
        float iv = sC[r * 200 + 3 * j + 0] + gc[n0 + 3 * j + 0];
        float gv = sC[r * 200 + 3 * j + 1] + gc[n0 + 3 * j + 1];
        float ov = sC[r * 200 + 3 * j + 2] + gc[n0 + 3 * j + 2];
        float cv = (1.f / (1.f + expf(-iv))) * tanhf(gv);
        float hv = (1.f / (1.f + expf(-ov))) * tanhf(cv);
        if (L0) {
            g_h1h[(size_t)(m0 + r) * 512 + cb + j] = __float2half(hv);
        } else {
            // fused FC: all 32 lanes of this warp share row r (j = lane + 0/32)
            float p0 = hv * w0, p1 = hv * w1;
            #pragma unroll
            for (int o = 16; o; o >>= 1) {
                p0 += __shfl_down_sync(0xffffffffu, p0, o);
                p1 += __shfl_down_sync(0xffffffffu, p1, o);
            }
            if (lane == 0) {
                atomicAdd(&e[(size_t)(m0 + r) * 2 + 0], p0);
                atomicAdd(&e[(size_t)(m0 + r) * 2 + 1], p1);
            }
        }
    }
}

// ---------------- CRF NLL: parallel log-semiring reduce ----------------------
__device__ __forceinline__ double lse2(double a, double b) {
    double m = fmax(a, b), n = fmin(a, b);
    return m + log1p(exp(n - m));
}

__global__ __launch_bounds__(256)
void crf_part(const float* __restrict__ e, const int* __restrict__ tags,
              const float* __restrict__ trans, int N) {
    __shared__ double sP[256][4];
    __shared__ double sN[256];
    const int t = threadIdx.x;
    const long n = (long)blockIdx.x * 256 + t;
    const double T00 = trans[0], T01 = trans[1], T10 = trans[2], T11 = trans[3];
    const double NEG = -1e30;

    double m00 = 0.0, m01 = NEG, m10 = NEG, m11 = 0.0;
    double np = 0.0;
    if (n < N) {
        int tg = tags[n];
        np = (double)e[n * 2 + tg];
        if (n >= 1) {
            int tp = tags[n - 1];
            np += (tp == 0) ? (tg == 0 ? T00 : T01) : (tg == 0 ? T10 : T11);
            double e0 = (double)e[n * 2 + 0];
            double e1 = (double)e[n * 2 + 1];
            m00 = T00 + e0; m01 = T01 + e1;
            m10 = T10 + e0; m11 = T11 + e1;
        }
    }
    sP[t][0] = m00; sP[t][1] = m01; sP[t][2] = m10; sP[t][3] = m11;
    sN[t] = np;
    __syncthreads();

    for (int half = 128; half >= 1; half >>= 1) {
        double a0, a1, a2, a3, b0, b1, b2, b3, nn;
        bool act = t < half;
        if (act) {
            a0 = sP[2 * t][0];     a1 = sP[2 * t][1];
            a2 = sP[2 * t][2];     a3 = sP[2 * t][3];
            b0 = sP[2 * t + 1][0]; b1 = sP[2 * t + 1][1];
            b2 = sP[2 * t + 1][2]; b3 = sP[2 * t + 1][3];
            nn = sN[2 * t] + sN[2 * t + 1];
        }
        __syncthreads();
        if (act) {
            sP[t][0] = lse2(a0 + b0, a1 + b2);
            sP[t][1] = lse2(a0 + b1, a1 + b3);
            sP[t][2] = lse2(a2 + b0, a3 + b2);
            sP[t][3] = lse2(a2 + b1, a3 + b3);
            sN[t] = nn;
        }
        __syncthreads();
    }
    if (t == 0) {
        g_crfP[blockIdx.x][0] = sP[0][0];
        g_crfP[blockIdx.x][1] = sP[0][1];
        g_crfP[blockIdx.x][2] = sP[0][2];
        g_crfP[blockIdx.x][3] = sP[0][3];
        g_crfN[blockIdx.x] = sN[0];
    }
}

__global__ __launch_bounds__(256)
void crf_comb(const float* __restrict__ e, const int* __restrict__ tags,
              const float* __restrict__ startv, const float* __restrict__ endv,
              float* __restrict__ loss_out, int N, int nb) {
    __shared__ double sP[256][4];
    __shared__ double sN[256];
    const int t = threadIdx.x;
    const double NEG = -1e30;
    if (t < nb) {
        sP[t][0] = g_crfP[t][0]; sP[t][1] = g_crfP[t][1];
        sP[t][2] = g_crfP[t][2]; sP[t][3] = g_crfP[t][3];
        sN[t] = g_crfN[t];
    } else {
        sP[t][0] = 0.0; sP[t][1] = NEG; sP[t][2] = NEG; sP[t][3] = 0.0;
        sN[t] = 0.0;
    }
    __syncthreads();

    for (int half = 128; half >= 1; half >>= 1) {
        double a0, a1, a2, a3, b0, b1, b2, b3, nn;
        bool act = t < half;
        if (act) {
            a0 = sP[2 * t][0];     a1 = sP[2 * t][1];
            a2 = sP[2 * t][2];     a3 = sP[2 * t][3];
            b0 = sP[2 * t + 1][0]; b1 = sP[2 * t + 1][1];
            b2 = sP[2 * t + 1][2]; b3 = sP[2 * t + 1][3];
            nn = sN[2 * t] + sN[2 * t + 1];
        }
        __syncthreads();
        if (act) {
            sP[t][0] = lse2(a0 + b0, a1 + b2);
            sP[t][1] = lse2(a0 + b1, a1 + b3);
            sP[t][2] = lse2(a2 + b0, a3 + b2);
            sP[t][3] = lse2(a2 + b1, a3 + b3);
            sN[t] = nn;
        }
        __syncthreads();
    }

    if (t == 0) {
        double num = sN[0] + (double)startv[tags[0]] + (double)endv[tags[N - 1]];
        double a0 = (double)startv[0] + (double)e[0];
        double a1 = (double)startv[1] + (double)e[1];
        double f0 = lse2(a0 + sP[0][0], a1 + sP[0][2]);
        double f1 = lse2(a0 + sP[0][1], a1 + sP[0][3]);
        double den = lse2(f0 + (double)endv[0], f1 + (double)endv[1]);
        loss_out[0] = (float)(den - num);
    }
}

// ---------------- launch ----------------
extern "C" void kernel_launch(void* const* d_in, const int* in_sizes, int n_in,
                              void* d_out, int out_size) {
    const float* x        = (const float*)d_in[0];
    const float* gamma    = (const float*)d_in[1];
    const float* beta     = (const float*)d_in[2];
    const float* w_ih_l0  = (const float*)d_in[3];
    const float* b_ih_l0  = (const float*)d_in[5];
    const float* b_hh_l0  = (const float*)d_in[6];
    const float* w_ih_l1  = (const float*)d_in[7];
    const float* b_ih_l1  = (const float*)d_in[9];
    const float* b_hh_l1  = (const float*)d_in[10];
    const float* fc_w     = (const float*)d_in[11];
    const float* fc_b     = (const float*)d_in[12];
    const float* crf_start= (const float*)d_in[13];
    const float* crf_end  = (const float*)d_in[14];
    const float* crf_trans= (const float*)d_in[15];
    const int*   labels   = (const int*)d_in[16];

    int N = in_sizes[0] / 768;      // 65536
    float* out = (float*)d_out;
    float* e = out + 1;

    cudaFuncSetAttribute((const void*)gemm_lstm_tc<true>,
                         cudaFuncAttributeMaxDynamicSharedMemorySize, SMEM_TC);
    cudaFuncSetAttribute((const void*)gemm_lstm_tc<false>,
                         cudaFuncAttributeMaxDynamicSharedMemorySize, SMEM_TC);

    int rpb = (N + 127) / 128;
    int nblk = (N + rpb - 1) / rpb;
    int nsplit = N * 768 / 4 / 256;                        // 49152

    stats_kernel<<<nblk, 768>>>(x, rpb, N);                                    // 0
    prep_kernel<<<1, 768>>>(gamma, beta, N, nblk);                             // 1
    prep_all_l0<<<nsplit + 4608 + 192, 256>>>((const float4*)x, w_ih_l0,
                                              b_ih_l0, b_hh_l0, nsplit);       // 2
    dim3 gg(8, N / 128);
    gemm_lstm_tc<true ><<<gg, 256, SMEM_TC>>>(fc_w, e);                        // 3  <- ncu
    prep_l1<<<3078 + (N + 255) / 256, 256>>>(w_ih_l1, b_ih_l1, b_hh_l1,
                                             fc_b, e, N);                      // 4
    gemm_lstm_tc<false><<<gg, 256, SMEM_TC>>>(fc_w, e);                        // 5
    crf_part<<<(N + 255) / 256, 256>>>(e, labels, crf_trans, N);               // 6
    crf_comb<<<1, 256>>>(e, labels, crf_start, crf_end, out, N, (N + 255) / 256); // 7
}

// round 15
// speedup vs baseline: 5.1357x; 1.0466x over previous
#include <cuda_runtime.h>
#include <cuda_fp16.h>
#include <math.h>
#include <stdint.h>

#define NROWS 65536

// ---------------- scratch (device globals; no allocation allowed) ----------
__device__ float  g_psum[128 * 768];
__device__ float  g_psumsq[128 * 768];
__device__ float  g_scale[768];
__device__ float  g_shift[768];
__device__ __half g_xh[(size_t)NROWS * 768];
__device__ __half g_W0[1536 * 768];
__device__ __half g_W1[1536 * 512];
__device__ __half g_h1h[(size_t)NROWS * 512];
__device__ float g_gc0[1536];
__device__ float g_gc1[1536];
__device__ double g_crfP[256][4];
__device__ double g_crfN[256];

// ---------------- helpers ----------------
__device__ __forceinline__ void cpasync16(uint32_t dst, const void* src) {
    asm volatile("cp.async.cg.shared.global [%0], [%1], 16;" :: "r"(dst), "l"(src));
}
#define CP_COMMIT() asm volatile("cp.async.commit_group;")

__device__ __forceinline__ void ldsm4(uint32_t& r0, uint32_t& r1, uint32_t& r2,
                                      uint32_t& r3, uint32_t addr) {
    asm volatile("ldmatrix.sync.aligned.m8n8.x4.shared.b16 {%0,%1,%2,%3}, [%4];"
                 : "=r"(r0), "=r"(r1), "=r"(r2), "=r"(r3) : "r"(addr));
}
__device__ __forceinline__ void mma16816h(float* c, const uint32_t* a, const uint32_t* b) {
    asm volatile("mma.sync.aligned.m16n8k16.row.col.f32.f16.f16.f32 "
                 "{%0,%1,%2,%3}, {%4,%5,%6,%7}, {%8,%9}, {%0,%1,%2,%3};"
                 : "+f"(c[0]), "+f"(c[1]), "+f"(c[2]), "+f"(c[3])
                 : "r"(a[0]), "r"(a[1]), "r"(a[2]), "r"(a[3]), "r"(b[0]), "r"(b[1]));
}

// ---------------- BN stats (per-block partials) -----------------------------
__global__ void stats_kernel(const float* __restrict__ x, int rowsPerBlock, int nrows) {
    int c = threadIdx.x;
    int b = blockIdx.x;
    long r0 = (long)b * rowsPerBlock;
    float s = 0.f, s2 = 0.f;
    for (int r = 0; r < rowsPerBlock; ++r) {
        long row = r0 + r;
        if (row < nrows) {
            float v = x[row * 768 + c];
            s += v; s2 += v * v;
        }
    }
    g_psum[b * 768 + c] = s;
    g_psumsq[b * 768 + c] = s2;
}

__global__ void prep_kernel(const float* __restrict__ gamma,
                            const float* __restrict__ beta, int nrows, int nblk) {
    int c = threadIdx.x;
    double s = 0.0, s2 = 0.0;
    for (int b = 0; b < nblk; ++b) {
        s  += (double)g_psum[b * 768 + c];
        s2 += (double)g_psumsq[b * 768 + c];
    }
    double mean = s / (double)nrows;
    double var  = s2 / (double)nrows - mean * mean;
    float sc = gamma[c] * (float)(1.0 / sqrt(var + 1e-5));
    g_scale[c] = sc;
    g_shift[c] = beta[c] - (float)mean * sc;
}

// ------------- merged L0 prep: split_x(fp16) + repackW0(fp16) + gconst0 ------
__global__ void prep_all_l0(const float4* __restrict__ x4,
                            const float* __restrict__ w,
                            const float* __restrict__ bih,
                            const float* __restrict__ bhh,
                            int nsplit) {
    int bid = blockIdx.x;
    int tid = threadIdx.x;
    if (bid < nsplit) {
        size_t i = (size_t)bid * 256 + tid;
        float4 v = x4[i];
        int c = (int)(i % 192) * 4;
        v.x *= g_scale[c + 0]; v.y *= g_scale[c + 1];
        v.z *= g_scale[c + 2]; v.w *= g_scale[c + 3];
        __half2* ph = (__half2*)g_xh;
        ph[i * 2 + 0] = __halves2half2(__float2half(v.x), __float2half(v.y));
        ph[i * 2 + 1] = __halves2half2(__float2half(v.z), __float2half(v.w));
    } else if (bid < nsplit + 4608) {
        int idx = (bid - nsplit) * 256 + tid;      // < 1536*768
        int d = idx % 768;
        int n = idx / 768;
        int g = n % 3, j = n / 3;
        int dir = j >> 8, jj = j & 255;
        int grow = (g == 0) ? jj : (g == 1 ? 512 + jj : 768 + jj);
        float v = w[(size_t)(dir * 1024 + grow) * 768 + d];
        g_W0[idx] = __float2half(v);
    } else {
        int warpId = (bid - nsplit - 4608) * 8 + (tid >> 5);   // < 1536
        int lane = tid & 31;
        int g = warpId % 3, j = warpId / 3;
        int dir = j >> 8, jj = j & 255;
        int grow = (g == 0) ? jj : (g == 1 ? 512 + jj : 768 + jj);
        const float* wr = w + (size_t)(dir * 1024 + grow) * 768;
        float s = 0.f;
        for (int k = lane; k < 768; k += 32) s += g_shift[k] * wr[k];
        #pragma unroll
        for (int o = 16; o; o >>= 1) s += __shfl_down_sync(0xffffffffu, s, o);
        if (!lane) g_gc0[warpId] = s + bih[dir * 1024 + grow] + bhh[dir * 1024 + grow];
    }
}

// ------------- merged L1 prep: repackW1(fp16) + gconst1 + e-bias init --------
__global__ void prep_l1(const float* __restrict__ w,
                        const float* __restrict__ bih,
                        const float* __restrict__ bhh,
                        const float* __restrict__ fcb,
                        float* __restrict__ e, int nrows) {
    int bid = blockIdx.x;
    int tid = threadIdx.x;
    if (bid < 3072) {
        int idx = bid * 256 + tid;                 // < 1536*512
        int d = idx % 512;
        int n = idx / 512;
        int g = n % 3, j = n / 3;
        int dir = j >> 8, jj = j & 255;
        int grow = (g == 0) ? jj : (g == 1 ? 512 + jj : 768 + jj);
        float v = w[(size_t)(dir * 1024 + grow) * 512 + d];
        g_W1[idx] = __float2half(v);
    } else if (bid < 3078) {
        int n = (bid - 3072) * 256 + tid;
        if (n >= 1536) return;
        int g = n % 3, j = n / 3;
        int dir = j >> 8, jj = j & 255;
        int grow = (g == 0) ? jj : (g == 1 ? 512 + jj : 768 + jj);
        g_gc1[n] = bih[dir * 1024 + grow] + bhh[dir * 1024 + grow];
    } else {
        int row = (bid - 3078) * 256 + tid;        // e bias init
        if (row < nrows) {
            e[(size_t)row * 2 + 0] = fcb[0];
            e[(size_t)row * 2 + 1] = fcb[1];
        }
    }
}

// ---------------- HMMA GEMM + fused LSTM (+FC for L1) epilogue --------------
// CTA 128 rows x 192 gate cols, 8 warps (2M x 4N), warp 64x48.
// Single fp16 product: acc += X*W. K-chunk 64, 2-stage pipeline, 2 CTAs/SM.
// Stage (stride 144B): A 128x144=18432 + B 192x144=27648 -> GBUF=46080.
#define GBUF   46080
#define OFF_B  18432
#define SMEM_TC 102400   // epilogue [128][200] floats dominates (2*GBUF=92160)

template <bool L0>
__global__ void __launch_bounds__(256, 2) gemm_lstm_tc(
        const float* __restrict__ fcw, float* __restrict__ e) {
    constexpr int K = L0 ? 768 : 512;
    constexpr int NCH = K / 64;
    const __half* __restrict__ Ah = L0 ? g_xh : g_h1h;
    const __half* __restrict__ Bw = L0 ? g_W0 : g_W1;
    const float* __restrict__ gc = L0 ? g_gc0 : g_gc1;

    extern __shared__ char smem[];
    uint32_t sbase = (uint32_t)__cvta_generic_to_shared(smem);

    const int tid = threadIdx.x;
    const int m0 = blockIdx.y * 128;
    const int n0 = blockIdx.x * 192;

    auto issue = [&](int kt, int b) {
        uint32_t sA = sbase + b * GBUF;
        const int r0 = tid >> 3, q = (tid & 7);
        #pragma unroll
        for (int it = 0; it < 4; ++it) {   // A: 128 rows x 8 x16B = 1024 transfers
            int r = r0 + it * 32;
            uint32_t d = sA + r * 144 + q * 16;
            const size_t go = (size_t)(m0 + r) * K + kt + q * 8;
            cpasync16(d, Ah + go);
        }
        #pragma unroll
        for (int it = 0; it < 6; ++it) {   // B: 192 rows x 8 x16B = 1536 transfers
            int r = r0 + it * 32;
            uint32_t d = sA + OFF_B + r * 144 + q * 16;
            const size_t go = (size_t)(n0 + r) * K + kt + q * 8;
            cpasync16(d, Bw + go);
        }
        CP_COMMIT();
    };

    const int lane = tid & 31, wid = tid >> 5;
    const int wm = (wid & 1) * 64;
    const int wn = (wid >> 1) * 48;

    const int msel   = lane >> 3;
    const int arow_f = (msel & 1) * 8 + (lane & 7);
    const int akoff  = (msel >> 1) * 8;
    const int brow_f = (msel >> 1) * 8 + (lane & 7);
    const int bkoff  = (msel & 1) * 8;

    float acc[4][6][4];
    #pragma unroll
    for (int mt = 0; mt < 4; mt++)
        #pragma unroll
        for (int nb = 0; nb < 6; nb++)
            #pragma unroll
            for (int r = 0; r < 4; r++) acc[mt][nb][r] = 0.f;

    issue(0, 0);
    issue(64, 1);

    #pragma unroll 1
    for (int c = 0; c < NCH; ++c) {
        asm volatile("cp.async.wait_group 1;" ::: "memory");
        __syncthreads();
        uint32_t sA = sbase + (c & 1) * GBUF;

        #pragma unroll
        for (int ks = 0; ks < 64; ks += 16) {
            uint32_t bw[6][2];
            #pragma unroll
            for (int p = 0; p < 3; p++) {
                uint32_t bd = sA + OFF_B + (wn + p * 16 + brow_f) * 144 + (ks + bkoff) * 2;
                ldsm4(bw[2 * p][0], bw[2 * p][1], bw[2 * p + 1][0], bw[2 * p + 1][1], bd);
            }
            #pragma unroll
            for (int mt = 0; mt < 4; mt++) {
                uint32_t ah[4];
                uint32_t ad = sA + (wm + mt * 16 + arow_f) * 144 + (ks + akoff) * 2;
                ldsm4(ah[0], ah[1], ah[2], ah[3], ad);
                #pragma unroll
                for (int nb = 0; nb < 6; nb++)
                    mma16816h(acc[mt][nb], ah, bw[nb]);
            }
        }
        __syncthreads();
        if (c + 2 < NCH) issue((c + 2) * 64, c & 1);
        else             CP_COMMIT();          // keep wait count uniform
    }

    float* sC = (float*)smem;
    #pragma unroll
    for (int mt = 0; mt < 4; mt++)
        #pragma unroll
        for (int nb = 0; nb < 6; nb++) {
            int r = wm + mt * 16 + (lane >> 2);
            int cc = wn + nb * 8 + (lane & 3) * 2;
            sC[r * 200 + cc]           = acc[mt][nb][0];
            sC[r * 200 + cc + 1]       = acc[mt][nb][1];
            sC[(r + 8) * 200 + cc]     = acc[mt][nb][2];
            sC[(r + 8) * 200 + cc + 1] = acc[mt][nb][3];
        }
    __syncthreads();

    const int cb = blockIdx.x * 64;
    const int jj = tid & 63;
    float w0 = 0.f, w1 = 0.f;
    if (!L0) {
        w0 = fcw[cb + jj];
        w1 = fcw[512 + cb + jj];
    }

    #pragma unroll
    for (int t = 0; t < 32; t++) {
        int idx = t * 256 + tid;
        int r = idx >> 6, j = idx & 63;
        float iv = sC[r * 200 + 3 * j + 0] + gc[n0 + 3 * j + 0];
        float gv = sC[r * 200 + 3 * j + 1] + gc[n0 + 3 * j + 1];
        float ov = sC[r * 200 + 3 * j + 2] + gc[n0 + 3 * j + 2];
        float cv = (1.f / (1.f + expf(-iv))) * tanhf(gv);
        float hv = (1.f / (1.f + expf(-ov))) * tanhf(cv);
        if (L0) {
            g_h1h[(size_t)(m0 + r) * 512 + cb + j] = __float2half(hv);
        } else {
            float p0 = hv * w0, p1 = hv * w1;
            #pragma unroll
            for (int o = 16; o; o >>= 1) {
                p0 += __shfl_down_sync(0xffffffffu, p0, o);
                p1 += __shfl_down_sync(0xffffffffu, p1, o);
            }
            if (lane == 0) {
                atomicAdd(&e[(size_t)(m0 + r) * 2 + 0], p0);
                atomicAdd(&e[(size_t)(m0 + r) * 2 + 1], p1);
            }
        }
    }
}

// ---------------- CRF NLL: parallel log-semiring reduce ----------------------
__device__ __forceinline__ double lse2(double a, double b) {
    double m = fmax(a, b), n = fmin(a, b);
    return m + log1p(exp(n - m));
}

__global__ __launch_bounds__(256)
void crf_part(const float* __restrict__ e, const int* __restrict__ tags,
              const float* __restrict__ trans, int N) {
    __shared__ double sP[256][4];
    __shared__ double sN[256];
    const int t = threadIdx.x;
    const long n = (long)blockIdx.x * 256 + t;
    const double T00 = trans[0], T01 = trans[1], T10 = trans[2], T11 = trans[3];
    const double NEG = -1e30;

    double m00 = 0.0, m01 = NEG, m10 = NEG, m11 = 0.0;
    double np = 0.0;
    if (n < N) {
        int tg = tags[n];
        np = (double)e[n * 2 + tg];
        if (n >= 1) {
            int tp = tags[n - 1];
            np += (tp == 0) ? (tg == 0 ? T00 : T01) : (tg == 0 ? T10 : T11);
            double e0 = (double)e[n * 2 + 0];
            double e1 = (double)e[n * 2 + 1];
            m00 = T00 + e0; m01 = T01 + e1;
            m10 = T10 + e0; m11 = T11 + e1;
        }
    }
    sP[t][0] = m00; sP[t][1] = m01; sP[t][2] = m10; sP[t][3] = m11;
    sN[t] = np;
    __syncthreads();

    for (int half = 128; half >= 1; half >>= 1) {
        double a0, a1, a2, a3, b0, b1, b2, b3, nn;
        bool act = t < half;
        if (act) {
            a0 = sP[2 * t][0];     a1 = sP[2 * t][1];
            a2 = sP[2 * t][2];     a3 = sP[2 * t][3];
            b0 = sP[2 * t + 1][0]; b1 = sP[2 * t + 1][1];
            b2 = sP[2 * t + 1][2]; b3 = sP[2 * t + 1][3];
            nn = sN[2 * t] + sN[2 * t + 1];
        }
        __syncthreads();
        if (act) {
            sP[t][0] = lse2(a0 + b0, a1 + b2);
            sP[t][1] = lse2(a0 + b1, a1 + b3);
            sP[t][2] = lse2(a2 + b0, a3 + b2);
            sP[t][3] = lse2(a2 + b1, a3 + b3);
            sN[t] = nn;
        }
        __syncthreads();
    }
    if (t == 0) {
        g_crfP[blockIdx.x][0] = sP[0][0];
        g_crfP[blockIdx.x][1] = sP[0][1];
        g_crfP[blockIdx.x][2] = sP[0][2];
        g_crfP[blockIdx.x][3] = sP[0][3];
        g_crfN[blockIdx.x] = sN[0];
    }
}

__global__ __launch_bounds__(256)
void crf_comb(const float* __restrict__ e, const int* __restrict__ tags,
              const float* __restrict__ startv, const float* __restrict__ endv,
              float* __restrict__ loss_out, int N, int nb) {
    __shared__ double sP[256][4];
    __shared__ double sN[256];
    const int t = threadIdx.x;
    const double NEG = -1e30;
    if (t < nb) {
        sP[t][0] = g_crfP[t][0]; sP[t][1] = g_crfP[t][1];
        sP[t][2] = g_crfP[t][2]; sP[t][3] = g_crfP[t][3];
        sN[t] = g_crfN[t];
    } else {
        sP[t][0] = 0.0; sP[t][1] = NEG; sP[t][2] = NEG; sP[t][3] = 0.0;
        sN[t] = 0.0;
    }
    __syncthreads();

    for (int half = 128; half >= 1; half >>= 1) {
        double a0, a1, a2, a3, b0, b1, b2, b3, nn;
        bool act = t < half;
        if (act) {
            a0 = sP[2 * t][0];     a1 = sP[2 * t][1];
            a2 = sP[2 * t][2];     a3 = sP[2 * t][3];
            b0 = sP[2 * t + 1][0]; b1 = sP[2 * t + 1][1];
            b2 = sP[2 * t + 1][2]; b3 = sP[2 * t + 1][3];
            nn = sN[2 * t] + sN[2 * t + 1];
        }
        __syncthreads();
        if (act) {
            sP[t][0] = lse2(a0 + b0, a1 + b2);
            sP[t][1] = lse2(a0 + b1, a1 + b3);
            sP[t][2] = lse2(a2 + b0, a3 + b2);
            sP[t][3] = lse2(a2 + b1, a3 + b3);
            sN[t] = nn;
        }
        __syncthreads();
    }

    if (t == 0) {
        double num = sN[0] + (double)startv[tags[0]] + (double)endv[tags[N - 1]];
        double a0 = (double)startv[0] + (double)e[0];
        double a1 = (double)startv[1] + (double)e[1];
        double f0 = lse2(a0 + sP[0][0], a1 + sP[0][2]);
        double f1 = lse2(a0 + sP[0][1], a1 + sP[0][3]);
        double den = lse2(f0 + (double)endv[0], f1 + (double)endv[1]);
        loss_out[0] = (float)(den - num);
    }
}

// ---------------- launch ----------------
extern "C" void kernel_launch(void* const* d_in, const int* in_sizes, int n_in,
                              void* d_out, int out_size) {
    const float* x        = (const float*)d_in[0];
    const float* gamma    = (const float*)d_in[1];
    const float* beta     = (const float*)d_in[2];
    const float* w_ih_l0  = (const float*)d_in[3];
    const float* b_ih_l0  = (const float*)d_in[5];
    const float* b_hh_l0  = (const float*)d_in[6];
    const float* w_ih_l1  = (const float*)d_in[7];
    const float* b_ih_l1  = (const float*)d_in[9];
    const float* b_hh_l1  = (const float*)d_in[10];
    const float* fc_w     = (const float*)d_in[11];
    const float* fc_b     = (const float*)d_in[12];
    const float* crf_start= (const float*)d_in[13];
    const float* crf_end  = (const float*)d_in[14];
    const float* crf_trans= (const float*)d_in[15];
    const int*   labels   = (const int*)d_in[16];

    int N = in_sizes[0] / 768;      // 65536
    float* out = (float*)d_out;
    float* e = out + 1;

    cudaFuncSetAttribute((const void*)gemm_lstm_tc<true>,
                         cudaFuncAttributeMaxDynamicSharedMemorySize, SMEM_TC);
    cudaFuncSetAttribute((const void*)gemm_lstm_tc<false>,
                         cudaFuncAttributeMaxDynamicSharedMemorySize, SMEM_TC);

    int rpb = (N + 127) / 128;
    int nblk = (N + rpb - 1) / rpb;
    int nsplit = N * 768 / 4 / 256;                        // 49152

    stats_kernel<<<nblk, 768>>>(x, rpb, N);                                    // 0
    prep_kernel<<<1, 768>>>(gamma, beta, N, nblk);                             // 1
    prep_all_l0<<<nsplit + 4608 + 192, 256>>>((const float4*)x, w_ih_l0,
                                              b_ih_l0, b_hh_l0, nsplit);       // 2
    dim3 gg(8, N / 128);
    gemm_lstm_tc<true ><<<gg, 256, SMEM_TC>>>(fc_w, e);                        // 3  <- ncu
    prep_l1<<<3078 + (N + 255) / 256, 256>>>(w_ih_l1, b_ih_l1, b_hh_l1,
                                             fc_b, e, N);                      // 4
    gemm_lstm_tc<false><<<gg, 256, SMEM_TC>>>(fc_w, e);                        // 5
    crf_part<<<(N + 255) / 256, 256>>>(e, labels, crf_trans, N);               // 6
    crf_comb<<<1, 256>>>(e, labels, crf_start, crf_end, out, N, (N + 255) / 256); // 7
}